// round 1
// baseline (speedup 1.0000x reference)
#include <cuda_runtime.h>
#include <math.h>

// ---------------- problem constants ----------------
namespace {
constexpr int B = 4, H = 64, W = 64, C = 768;
constexpr int HEADS = 12, HD = 64, WS = 14, HID = 3072;
constexpr int NWIN = 5;               // 70/14
constexpr int NWB  = NWIN * NWIN;     // 25 windows per batch
constexpr int NW   = B * NWB;         // 100 windows
constexpr int L    = WS * WS;         // 196 tokens per window
constexpr int NT   = NW * L;          // 19600 window tokens
constexpr int NP   = B * H * W;       // 16384 real pixels
constexpr int C3   = 3 * C;           // 2304
constexpr int RELN = 2 * WS - 1;      // 27
constexpr float EPS   = 1e-6f;
constexpr float SCALE = 0.125f;       // HD^-0.5
}

// ---------------- scratch (device globals; no allocation allowed) --------
__device__ float g_ywin[(size_t)NT * C];    // LN1 output in window layout
__device__ float g_qkv [(size_t)NT * C3];   // qkv
__device__ float g_owin[(size_t)NT * C];    // attention output (window layout)
__device__ float g_x1  [(size_t)NP * C];    // shortcut + proj(o)
__device__ float g_h2  [(size_t)NP * C];    // LN2 output
__device__ float g_m1  [(size_t)NP * HID];  // gelu(fc1)

// window-row -> pixel-row index (-1 if padded)
__device__ __forceinline__ int winrow_to_pixel(int t) {
    int nw = t / L, l = t - nw * L;
    int b  = nw / NWB, r = nw - b * NWB;
    int wi = r / NWIN, wj = r - wi * NWIN;
    int i  = l / WS,   j  = l - i * WS;
    int hh = wi * WS + i, ww = wj * WS + j;
    if (hh >= H || ww >= W) return -1;
    return (b * H + hh) * W + ww;
}

// ---------------- LN1 + window gather (zero-fill padding) ----------------
__global__ void ln1_gather_kernel(const float* __restrict__ x,
                                  const float* __restrict__ sc,
                                  const float* __restrict__ bi) {
    int t = blockIdx.x;
    int tid = threadIdx.x;
    float* y = g_ywin + (size_t)t * C;
    int pix = winrow_to_pixel(t);
    if (pix < 0) {
        for (int c = tid; c < C; c += blockDim.x) y[c] = 0.f;
        return;
    }
    const float* xr = x + (size_t)pix * C;
    float s = 0.f, s2 = 0.f;
    for (int c = tid; c < C; c += blockDim.x) { float v = xr[c]; s += v; s2 += v * v; }
    __shared__ float red[64];
    for (int o = 16; o; o >>= 1) {
        s  += __shfl_xor_sync(0xffffffffu, s, o);
        s2 += __shfl_xor_sync(0xffffffffu, s2, o);
    }
    int warp = tid >> 5, lane = tid & 31;
    if (!lane) { red[warp] = s; red[32 + warp] = s2; }
    __syncthreads();
    if (tid < 32) {
        float a  = (tid < 8) ? red[tid]      : 0.f;
        float b2 = (tid < 8) ? red[32 + tid] : 0.f;
        for (int o = 4; o; o >>= 1) {
            a  += __shfl_xor_sync(0xffffffffu, a, o);
            b2 += __shfl_xor_sync(0xffffffffu, b2, o);
        }
        if (!tid) { red[0] = a; red[1] = b2; }
    }
    __syncthreads();
    float mu  = red[0] / (float)C;
    float var = red[1] / (float)C - mu * mu;
    float inv = rsqrtf(var + EPS);
    for (int c = tid; c < C; c += blockDim.x)
        y[c] = (xr[c] - mu) * inv * sc[c] + bi[c];
}

// ---------------- LN over contiguous rows (x1 -> h2) ---------------------
__global__ void ln_rows_kernel(const float* __restrict__ in,
                               const float* __restrict__ sc,
                               const float* __restrict__ bi,
                               float* __restrict__ out) {
    int t = blockIdx.x;
    int tid = threadIdx.x;
    const float* xr = in + (size_t)t * C;
    float* y = out + (size_t)t * C;
    float s = 0.f, s2 = 0.f;
    for (int c = tid; c < C; c += blockDim.x) { float v = xr[c]; s += v; s2 += v * v; }
    __shared__ float red[64];
    for (int o = 16; o; o >>= 1) {
        s  += __shfl_xor_sync(0xffffffffu, s, o);
        s2 += __shfl_xor_sync(0xffffffffu, s2, o);
    }
    int warp = tid >> 5, lane = tid & 31;
    if (!lane) { red[warp] = s; red[32 + warp] = s2; }
    __syncthreads();
    if (tid < 32) {
        float a  = (tid < 8) ? red[tid]      : 0.f;
        float b2 = (tid < 8) ? red[32 + tid] : 0.f;
        for (int o = 4; o; o >>= 1) {
            a  += __shfl_xor_sync(0xffffffffu, a, o);
            b2 += __shfl_xor_sync(0xffffffffu, b2, o);
        }
        if (!tid) { red[0] = a; red[1] = b2; }
    }
    __syncthreads();
    float mu  = red[0] / (float)C;
    float var = red[1] / (float)C - mu * mu;
    float inv = rsqrtf(var + EPS);
    for (int c = tid; c < C; c += blockDim.x)
        y[c] = (xr[c] - mu) * inv * sc[c] + bi[c];
}

// ---------------- tiled SGEMM with fused epilogues ------------------------
// MODE 0: Cout[m,n] = acc + bias[n]                        (qkv)
// MODE 1: pixel scatter: x1[pix,n] = x[pix,n] + acc+bias   (proj + residual)
// MODE 2: Cout[m,n] = gelu(acc + bias[n])                  (fc1)
// MODE 3: Cout[m,n] = aux[m,n] + acc + bias[n]             (fc2 + residual)
template <int MODE>
__global__ void sgemm_kernel(const float* __restrict__ A,
                             const float* __restrict__ Bm,
                             const float* __restrict__ bias,
                             const float* __restrict__ aux,
                             float* __restrict__ Cout,
                             int M, int N, int K) {
    constexpr int BM = 64, BN = 64, BK = 16;
    __shared__ float As[BK][BM + 4];
    __shared__ float Bs[BK][BN + 4];
    int row0 = blockIdx.y * BM, col0 = blockIdx.x * BN;
    int tid = threadIdx.x;
    int tx = tid & 15, ty = tid >> 4;
    float acc[4][4] = {};

    for (int k0 = 0; k0 < K; k0 += BK) {
#pragma unroll
        for (int i = 0; i < 4; i++) {
            int idx = tid + i * 256;
            int m = idx >> 4, kk = idx & 15;
            int gr = row0 + m;
            As[kk][m] = (gr < M) ? A[(size_t)gr * K + k0 + kk] : 0.f;
        }
#pragma unroll
        for (int i = 0; i < 4; i++) {
            int idx = tid + i * 256;
            int n = idx & 63, kk = idx >> 6;
            Bs[kk][n] = Bm[(size_t)(k0 + kk) * N + col0 + n];
        }
        __syncthreads();
#pragma unroll
        for (int kk = 0; kk < BK; kk++) {
            float a[4], b[4];
#pragma unroll
            for (int i = 0; i < 4; i++) a[i] = As[kk][ty * 4 + i];
#pragma unroll
            for (int j = 0; j < 4; j++) b[j] = Bs[kk][tx * 4 + j];
#pragma unroll
            for (int i = 0; i < 4; i++)
#pragma unroll
                for (int j = 0; j < 4; j++)
                    acc[i][j] = fmaf(a[i], b[j], acc[i][j]);
        }
        __syncthreads();
    }

#pragma unroll
    for (int i = 0; i < 4; i++) {
        int m = row0 + ty * 4 + i;
        if (m >= M) continue;
        int pix = -1;
        if (MODE == 1) pix = winrow_to_pixel(m);
#pragma unroll
        for (int j = 0; j < 4; j++) {
            int n = col0 + tx * 4 + j;
            float v = acc[i][j] + bias[n];
            if (MODE == 0) {
                Cout[(size_t)m * N + n] = v;
            } else if (MODE == 1) {
                if (pix >= 0)
                    Cout[(size_t)pix * N + n] = aux[(size_t)pix * N + n] + v;
            } else if (MODE == 2) {
                Cout[(size_t)m * N + n] = 0.5f * v * (1.f + erff(v * 0.70710678118654752f));
            } else {
                Cout[(size_t)m * N + n] = aux[(size_t)m * N + n] + v;
            }
        }
    }
}

// ---------------- fused attention: scores + rel-pos bias + softmax + AV --
// one block per (window, head); K/V/rel tables staged in dynamic smem
constexpr int ATTN_SMEM_FLOATS =
    L * 65 +      // Ks (padded stride)
    L * 64 +      // Vs
    RELN * 65 +   // RH (padded)
    RELN * 65 +   // RW
    64 +          // qv
    256 +         // pp (probs)
    32 +          // red
    256;          // partial
constexpr int ATTN_SMEM_BYTES = ATTN_SMEM_FLOATS * 4;

__global__ void attn_kernel(const float* __restrict__ rph,
                            const float* __restrict__ rpw) {
    extern __shared__ float sm[];
    float* Ks = sm;
    float* Vs = Ks + L * 65;
    float* RH = Vs + L * 64;
    float* RW = RH + RELN * 65;
    float* qv = RW + RELN * 65;
    float* pp = qv + 64;
    float* red = pp + 256;
    float* partial = red + 32;

    int blk = blockIdx.x;
    int nw = blk / HEADS, head = blk - nw * HEADS;
    int tid = threadIdx.x;
    size_t base = (size_t)nw * L * C3 + head * HD;

    for (int idx = tid; idx < L * HD; idx += 256) {
        int l = idx >> 6, d = idx & 63;
        Ks[l * 65 + d] = g_qkv[base + (size_t)l * C3 + C + d];
        Vs[l * 64 + d] = g_qkv[base + (size_t)l * C3 + 2 * C + d];
    }
    for (int idx = tid; idx < RELN * HD; idx += 256) {
        int r = idx >> 6, d = idx & 63;
        RH[r * 65 + d] = rph[idx];
        RW[r * 65 + d] = rpw[idx];
    }
    __syncthreads();

    for (int q = 0; q < L; q++) {
        if (tid < HD) qv[tid] = g_qkv[base + (size_t)q * C3 + tid];
        __syncthreads();

        int qi = q / WS, qj = q - qi * WS;
        float lt = -1e30f;
        if (tid < L) {
            int ki = tid / WS, kj = tid - ki * WS;
            const float* kr = Ks + tid * 65;
            const float* rh = RH + (qi - ki + WS - 1) * 65;
            const float* rw = RW + (qj - kj + WS - 1) * 65;
            float s = 0.f, bh = 0.f, bw = 0.f;
#pragma unroll 16
            for (int d = 0; d < HD; d++) {
                float qd = qv[d];
                s  = fmaf(qd, kr[d], s);
                bh = fmaf(qd, rh[d], bh);
                bw = fmaf(qd, rw[d], bw);
            }
            lt = s * SCALE + bh + bw;
        }

        // block max
        float v = lt;
        for (int o = 16; o; o >>= 1) v = fmaxf(v, __shfl_xor_sync(0xffffffffu, v, o));
        if ((tid & 31) == 0) red[tid >> 5] = v;
        __syncthreads();
        if (tid < 32) {
            float w = (tid < 8) ? red[tid] : -1e30f;
            for (int o = 4; o; o >>= 1) w = fmaxf(w, __shfl_xor_sync(0xffffffffu, w, o));
            if (tid == 0) red[0] = w;
        }
        __syncthreads();
        float mx = red[0];
        float e = (tid < L) ? expf(lt - mx) : 0.f;
        pp[tid] = e;
        __syncthreads();   // everyone has read mx before red is reused

        // block sum
        float sv = e;
        for (int o = 16; o; o >>= 1) sv += __shfl_xor_sync(0xffffffffu, sv, o);
        if ((tid & 31) == 0) red[tid >> 5] = sv;
        __syncthreads();
        if (tid < 32) {
            float w = (tid < 8) ? red[tid] : 0.f;
            for (int o = 4; o; o >>= 1) w += __shfl_xor_sync(0xffffffffu, w, o);
            if (tid == 0) red[0] = w;
        }
        __syncthreads();
        float inv = 1.f / red[0];

        // AV: 64 d-lanes x 4 k-groups
        int d = tid & 63, g = tid >> 6;
        float acc = 0.f;
        for (int k = g; k < L; k += 4) acc = fmaf(pp[k], Vs[k * 64 + d], acc);
        partial[tid] = acc;
        __syncthreads();
        if (tid < 64) {
            float o = (partial[tid] + partial[tid + 64] + partial[tid + 128] + partial[tid + 192]) * inv;
            g_owin[((size_t)nw * L + q) * C + head * HD + tid] = o;
        }
        __syncthreads();
    }
}

// ---------------- launch ---------------------------------------------------
extern "C" void kernel_launch(void* const* d_in, const int* in_sizes, int n_in,
                              void* d_out, int out_size) {
    const float* x      = (const float*)d_in[0];
    const float* n1s    = (const float*)d_in[1];
    const float* n1b    = (const float*)d_in[2];
    const float* qkvw   = (const float*)d_in[3];
    const float* qkvb   = (const float*)d_in[4];
    const float* rph    = (const float*)d_in[5];
    const float* rpw    = (const float*)d_in[6];
    const float* projw  = (const float*)d_in[7];
    const float* projb  = (const float*)d_in[8];
    const float* n2s    = (const float*)d_in[9];
    const float* n2b    = (const float*)d_in[10];
    const float* fc1w   = (const float*)d_in[11];
    const float* fc1b   = (const float*)d_in[12];
    const float* fc2w   = (const float*)d_in[13];
    const float* fc2b   = (const float*)d_in[14];
    float* out = (float*)d_out;

    static bool attr_set = false;
    // idempotent, non-stream API; safe under graph capture
    cudaFuncSetAttribute(attn_kernel, cudaFuncAttributeMaxDynamicSharedMemorySize,
                         ATTN_SMEM_BYTES);
    (void)attr_set;

    float* ywin; cudaGetSymbolAddress((void**)&ywin, g_ywin);
    float* qkv;  cudaGetSymbolAddress((void**)&qkv,  g_qkv);
    float* owin; cudaGetSymbolAddress((void**)&owin, g_owin);
    float* x1;   cudaGetSymbolAddress((void**)&x1,   g_x1);
    float* h2;   cudaGetSymbolAddress((void**)&h2,   g_h2);
    float* m1;   cudaGetSymbolAddress((void**)&m1,   g_m1);

    // 1) LN1 + window partition (zero-pad)
    ln1_gather_kernel<<<NT, 256>>>(x, n1s, n1b);

    // 2) qkv = ywin @ qkv_w + qkv_b           (19600 x 2304 x 768)
    {
        dim3 grid(C3 / 64, (NT + 63) / 64);
        sgemm_kernel<0><<<grid, 256>>>(ywin, qkvw, qkvb, nullptr, qkv, NT, C3, C);
    }

    // 3) fused windowed attention with decomposed rel-pos bias
    attn_kernel<<<NW * HEADS, 256, ATTN_SMEM_BYTES>>>(rph, rpw);

    // 4) x1 = shortcut + (owin @ proj_w + proj_b)  (scatter, crop padding)
    {
        dim3 grid(C / 64, (NT + 63) / 64);
        sgemm_kernel<1><<<grid, 256>>>(owin, projw, projb, x, x1, NT, C, C);
    }

    // 5) LN2
    ln_rows_kernel<<<NP, 256>>>(x1, n2s, n2b, h2);

    // 6) m1 = gelu(h2 @ fc1_w + fc1_b)        (16384 x 3072 x 768)
    {
        dim3 grid(HID / 64, NP / 64);
        sgemm_kernel<2><<<grid, 256>>>(h2, fc1w, fc1b, nullptr, m1, NP, HID, C);
    }

    // 7) out = x1 + m1 @ fc2_w + fc2_b        (16384 x 768 x 3072)
    {
        dim3 grid(C / 64, NP / 64);
        sgemm_kernel<3><<<grid, 256>>>(m1, fc2w, fc2b, x1, out, NP, C, HID);
    }
}

// round 2
// speedup vs baseline: 1.5064x; 1.5064x over previous
#include <cuda_runtime.h>
#include <math.h>

// ---------------- problem constants ----------------
namespace {
constexpr int B = 4, H = 64, W = 64, C = 768;
constexpr int HEADS = 12, HD = 64, WS = 14, HID = 3072;
constexpr int NWIN = 5;               // 70/14
constexpr int NWB  = NWIN * NWIN;     // 25 windows per batch
constexpr int NW   = B * NWB;         // 100 windows
constexpr int L    = WS * WS;         // 196 tokens per window
constexpr int NT   = NW * L;          // 19600 window tokens
constexpr int NP   = B * H * W;       // 16384 real pixels
constexpr int C3   = 3 * C;           // 2304
constexpr int RELN = 2 * WS - 1;      // 27
constexpr float EPS   = 1e-6f;
constexpr float SCALE = 0.125f;       // HD^-0.5
}

// ---------------- scratch (device globals; no allocation allowed) --------
__device__ float g_ywin[(size_t)NT * C];    // LN1 output in window layout
__device__ float g_qkv [(size_t)NT * C3];   // qkv
__device__ float g_owin[(size_t)NT * C];    // attention output (window layout)
__device__ float g_x1  [(size_t)NP * C];    // shortcut + proj(o)
__device__ float g_h2  [(size_t)NP * C];    // LN2 output
__device__ float g_m1  [(size_t)NP * HID];  // gelu(fc1)

// window-row -> pixel-row index (-1 if padded)
__device__ __forceinline__ int winrow_to_pixel(int t) {
    int nw = t / L, l = t - nw * L;
    int b  = nw / NWB, r = nw - b * NWB;
    int wi = r / NWIN, wj = r - wi * NWIN;
    int i  = l / WS,   j  = l - i * WS;
    int hh = wi * WS + i, ww = wj * WS + j;
    if (hh >= H || ww >= W) return -1;
    return (b * H + hh) * W + ww;
}

// ---------------- LN1 + window gather (zero-fill padding) ----------------
__global__ void ln1_gather_kernel(const float* __restrict__ x,
                                  const float* __restrict__ sc,
                                  const float* __restrict__ bi) {
    int t = blockIdx.x;
    int tid = threadIdx.x;
    float* y = g_ywin + (size_t)t * C;
    int pix = winrow_to_pixel(t);
    if (pix < 0) {
        for (int c = tid; c < C; c += blockDim.x) y[c] = 0.f;
        return;
    }
    const float* xr = x + (size_t)pix * C;
    float s = 0.f, s2 = 0.f;
    for (int c = tid; c < C; c += blockDim.x) { float v = xr[c]; s += v; s2 += v * v; }
    __shared__ float red[64];
    for (int o = 16; o; o >>= 1) {
        s  += __shfl_xor_sync(0xffffffffu, s, o);
        s2 += __shfl_xor_sync(0xffffffffu, s2, o);
    }
    int warp = tid >> 5, lane = tid & 31;
    if (!lane) { red[warp] = s; red[32 + warp] = s2; }
    __syncthreads();
    if (tid < 32) {
        float a  = (tid < 8) ? red[tid]      : 0.f;
        float b2 = (tid < 8) ? red[32 + tid] : 0.f;
        for (int o = 4; o; o >>= 1) {
            a  += __shfl_xor_sync(0xffffffffu, a, o);
            b2 += __shfl_xor_sync(0xffffffffu, b2, o);
        }
        if (!tid) { red[0] = a; red[1] = b2; }
    }
    __syncthreads();
    float mu  = red[0] / (float)C;
    float var = red[1] / (float)C - mu * mu;
    float inv = rsqrtf(var + EPS);
    for (int c = tid; c < C; c += blockDim.x)
        y[c] = (xr[c] - mu) * inv * sc[c] + bi[c];
}

// ---------------- LN over contiguous rows (x1 -> h2) ---------------------
__global__ void ln_rows_kernel(const float* __restrict__ in,
                               const float* __restrict__ sc,
                               const float* __restrict__ bi,
                               float* __restrict__ out) {
    int t = blockIdx.x;
    int tid = threadIdx.x;
    const float* xr = in + (size_t)t * C;
    float* y = out + (size_t)t * C;
    float s = 0.f, s2 = 0.f;
    for (int c = tid; c < C; c += blockDim.x) { float v = xr[c]; s += v; s2 += v * v; }
    __shared__ float red[64];
    for (int o = 16; o; o >>= 1) {
        s  += __shfl_xor_sync(0xffffffffu, s, o);
        s2 += __shfl_xor_sync(0xffffffffu, s2, o);
    }
    int warp = tid >> 5, lane = tid & 31;
    if (!lane) { red[warp] = s; red[32 + warp] = s2; }
    __syncthreads();
    if (tid < 32) {
        float a  = (tid < 8) ? red[tid]      : 0.f;
        float b2 = (tid < 8) ? red[32 + tid] : 0.f;
        for (int o = 4; o; o >>= 1) {
            a  += __shfl_xor_sync(0xffffffffu, a, o);
            b2 += __shfl_xor_sync(0xffffffffu, b2, o);
        }
        if (!tid) { red[0] = a; red[1] = b2; }
    }
    __syncthreads();
    float mu  = red[0] / (float)C;
    float var = red[1] / (float)C - mu * mu;
    float inv = rsqrtf(var + EPS);
    for (int c = tid; c < C; c += blockDim.x)
        y[c] = (xr[c] - mu) * inv * sc[c] + bi[c];
}

// ---------------- 128x128x8 double-buffered SGEMM, 8x8 microtile ---------
// MODE 0: Cout[m,n] = acc + bias[n]                        (qkv)
// MODE 1: pixel scatter: x1[pix,n] = x[pix,n] + acc+bias   (proj + residual)
// MODE 2: Cout[m,n] = gelu(acc + bias[n])                  (fc1)
// MODE 3: Cout[m,n] = aux[m,n] + acc + bias[n]             (fc2 + residual)
template <int MODE>
__global__ void __launch_bounds__(256, 2)
sgemm128_kernel(const float* __restrict__ A,
                const float* __restrict__ Bm,
                const float* __restrict__ bias,
                const float* __restrict__ aux,
                float* __restrict__ Cout,
                int M, int N, int K) {
    constexpr int BM = 128, BN = 128, BK = 8, SP = 132;
    __shared__ float As[2][BK][SP];
    __shared__ float Bs[2][BK][SP];

    int tid = threadIdx.x;
    int row0 = blockIdx.y * BM, col0 = blockIdx.x * BN;
    int tx = tid & 15, ty = tid >> 4;

    // A load: thread -> (am, ak) covering 128x8 with one float4 each
    int am = tid >> 1;
    int ak = (tid & 1) * 4;
    // B load: thread -> (bk, bn) covering 8x128 with one float4 each
    int bk = tid >> 5;
    int bn = (tid & 31) * 4;

    bool arow_ok = (row0 + am) < M;
    const float* Aptr = A + (size_t)(row0 + am) * K + ak;
    const float* Bptr = Bm + (size_t)bk * N + col0 + bn;

    float4 ar = arow_ok ? *(const float4*)Aptr : make_float4(0.f, 0.f, 0.f, 0.f);
    float4 br = *(const float4*)Bptr;
    As[0][ak + 0][am] = ar.x;
    As[0][ak + 1][am] = ar.y;
    As[0][ak + 2][am] = ar.z;
    As[0][ak + 3][am] = ar.w;
    *(float4*)&Bs[0][bk][bn] = br;
    __syncthreads();

    float acc[8][8] = {};
    int nk = K / BK;
    int buf = 0;

    for (int t = 0; t < nk; t++) {
        if (t + 1 < nk) {
            const float* Ap = Aptr + (t + 1) * BK;
            ar = arow_ok ? *(const float4*)Ap : make_float4(0.f, 0.f, 0.f, 0.f);
            br = *(const float4*)(Bptr + (size_t)(t + 1) * BK * N);
        }
#pragma unroll
        for (int kk = 0; kk < BK; kk++) {
            float4 a0 = *(const float4*)&As[buf][kk][ty * 4];
            float4 a1 = *(const float4*)&As[buf][kk][ty * 4 + 64];
            float4 b0 = *(const float4*)&Bs[buf][kk][tx * 4];
            float4 b1 = *(const float4*)&Bs[buf][kk][tx * 4 + 64];
            float a[8] = {a0.x, a0.y, a0.z, a0.w, a1.x, a1.y, a1.z, a1.w};
            float b[8] = {b0.x, b0.y, b0.z, b0.w, b1.x, b1.y, b1.z, b1.w};
#pragma unroll
            for (int i = 0; i < 8; i++)
#pragma unroll
                for (int j = 0; j < 8; j++)
                    acc[i][j] = fmaf(a[i], b[j], acc[i][j]);
        }
        if (t + 1 < nk) {
            buf ^= 1;
            As[buf][ak + 0][am] = ar.x;
            As[buf][ak + 1][am] = ar.y;
            As[buf][ak + 2][am] = ar.z;
            As[buf][ak + 3][am] = ar.w;
            *(float4*)&Bs[buf][bk][bn] = br;
            __syncthreads();
        }
    }

#pragma unroll
    for (int i = 0; i < 8; i++) {
        int mrow = row0 + ((i < 4) ? (ty * 4 + i) : (64 + ty * 4 + i - 4));
        if (mrow >= M) continue;
        int pix = -1;
        if (MODE == 1) pix = winrow_to_pixel(mrow);
#pragma unroll
        for (int j = 0; j < 8; j++) {
            int ncol = col0 + ((j < 4) ? (tx * 4 + j) : (64 + tx * 4 + j - 4));
            float v = acc[i][j] + bias[ncol];
            if (MODE == 0) {
                Cout[(size_t)mrow * N + ncol] = v;
            } else if (MODE == 1) {
                if (pix >= 0)
                    Cout[(size_t)pix * N + ncol] = aux[(size_t)pix * N + ncol] + v;
            } else if (MODE == 2) {
                Cout[(size_t)mrow * N + ncol] =
                    0.5f * v * (1.f + erff(v * 0.70710678118654752f));
            } else {
                Cout[(size_t)mrow * N + ncol] = aux[(size_t)mrow * N + ncol] + v;
            }
        }
    }
}

// ---------------- fused attention: warp-per-query, no block barriers ------
constexpr int QSPLIT = 2;
constexpr int QPB = (L + QSPLIT - 1) / QSPLIT;   // 98
constexpr int ATTN_SMEM_FLOATS =
    L * 65 +        // Ks (padded)
    L * 64 +        // Vs
    RELN * 65 +     // RH
    RELN * 65 +     // RW
    8 * 66 +        // per-warp q
    8 * 200;        // per-warp probs
constexpr int ATTN_SMEM_BYTES = ATTN_SMEM_FLOATS * 4;

__global__ void attn_kernel(const float* __restrict__ rph,
                            const float* __restrict__ rpw) {
    extern __shared__ float sm[];
    float* Ks = sm;
    float* Vs = Ks + L * 65;
    float* RH = Vs + L * 64;
    float* RW = RH + RELN * 65;
    float* qb = RW + RELN * 65;
    float* pb = qb + 8 * 66;

    int blk = blockIdx.x;
    int part = blk & (QSPLIT - 1);
    int wh = blk / QSPLIT;
    int nw = wh / HEADS, head = wh - nw * HEADS;
    int tid = threadIdx.x;
    size_t base = (size_t)nw * L * C3 + head * HD;

    for (int idx = tid; idx < L * HD; idx += 256) {
        int l = idx >> 6, d = idx & 63;
        Ks[l * 65 + d] = g_qkv[base + (size_t)l * C3 + C + d];
        Vs[l * 64 + d] = g_qkv[base + (size_t)l * C3 + 2 * C + d];
    }
    for (int idx = tid; idx < RELN * HD; idx += 256) {
        int r = idx >> 6, d = idx & 63;
        RH[r * 65 + d] = rph[idx];
        RW[r * 65 + d] = rpw[idx];
    }
    __syncthreads();

    int warp = tid >> 5, lane = tid & 31;
    float* qv = qb + warp * 66;
    float* prob = pb + warp * 200;
    int qend = min(L, (part + 1) * QPB);

    for (int q = part * QPB + warp; q < qend; q += 8) {
        qv[lane]      = g_qkv[base + (size_t)q * C3 + lane];
        qv[32 + lane] = g_qkv[base + (size_t)q * C3 + 32 + lane];
        __syncwarp();

        int qi = q / WS, qj = q - qi * WS;

        // 7 key slots per lane, interleaved accumulation over d
        const float* kr[7];
        const float* rh[7];
        const float* rw[7];
        bool ok[7];
        float s0[7], bh[7], bw[7];
#pragma unroll
        for (int s = 0; s < 7; s++) {
            int k = lane + 32 * s;
            ok[s] = (k < L);
            int kc = ok[s] ? k : (L - 1);
            int ki = kc / WS, kj = kc - ki * WS;
            kr[s] = Ks + kc * 65;
            rh[s] = RH + (qi - ki + WS - 1) * 65;
            rw[s] = RW + (qj - kj + WS - 1) * 65;
            s0[s] = 0.f; bh[s] = 0.f; bw[s] = 0.f;
        }
#pragma unroll 8
        for (int d = 0; d < HD; d++) {
            float qd = qv[d];
#pragma unroll
            for (int s = 0; s < 7; s++) {
                s0[s] = fmaf(qd, kr[s][d], s0[s]);
                bh[s] = fmaf(qd, rh[s][d], bh[s]);
                bw[s] = fmaf(qd, rw[s][d], bw[s]);
            }
        }
        float lt[7];
#pragma unroll
        for (int s = 0; s < 7; s++)
            lt[s] = ok[s] ? (s0[s] * SCALE + bh[s] + bw[s]) : -1e30f;

        // warp softmax
        float mx = lt[0];
#pragma unroll
        for (int s = 1; s < 7; s++) mx = fmaxf(mx, lt[s]);
        for (int o = 16; o; o >>= 1) mx = fmaxf(mx, __shfl_xor_sync(0xffffffffu, mx, o));
        float sum = 0.f;
#pragma unroll
        for (int s = 0; s < 7; s++) { lt[s] = expf(lt[s] - mx); sum += lt[s]; }
        for (int o = 16; o; o >>= 1) sum += __shfl_xor_sync(0xffffffffu, sum, o);
        float inv = 1.f / sum;
#pragma unroll
        for (int s = 0; s < 7; s++) {
            int k = lane + 32 * s;
            if (k < L) prob[k] = lt[s] * inv;
        }
        __syncwarp();

        // AV: each lane owns 2 output dims
        int d0 = lane * 2;
        float ax = 0.f, ay = 0.f;
#pragma unroll 4
        for (int k = 0; k < L; k++) {
            float p = prob[k];
            float2 v = *(const float2*)&Vs[k * 64 + d0];
            ax = fmaf(p, v.x, ax);
            ay = fmaf(p, v.y, ay);
        }
        float2 o2 = make_float2(ax, ay);
        *(float2*)&g_owin[((size_t)nw * L + q) * C + head * HD + d0] = o2;
        __syncwarp();
    }
}

// ---------------- launch ---------------------------------------------------
extern "C" void kernel_launch(void* const* d_in, const int* in_sizes, int n_in,
                              void* d_out, int out_size) {
    const float* x      = (const float*)d_in[0];
    const float* n1s    = (const float*)d_in[1];
    const float* n1b    = (const float*)d_in[2];
    const float* qkvw   = (const float*)d_in[3];
    const float* qkvb   = (const float*)d_in[4];
    const float* rph    = (const float*)d_in[5];
    const float* rpw    = (const float*)d_in[6];
    const float* projw  = (const float*)d_in[7];
    const float* projb  = (const float*)d_in[8];
    const float* n2s    = (const float*)d_in[9];
    const float* n2b    = (const float*)d_in[10];
    const float* fc1w   = (const float*)d_in[11];
    const float* fc1b   = (const float*)d_in[12];
    const float* fc2w   = (const float*)d_in[13];
    const float* fc2b   = (const float*)d_in[14];
    float* out = (float*)d_out;

    cudaFuncSetAttribute(attn_kernel, cudaFuncAttributeMaxDynamicSharedMemorySize,
                         ATTN_SMEM_BYTES);

    float* ywin; cudaGetSymbolAddress((void**)&ywin, g_ywin);
    float* qkv;  cudaGetSymbolAddress((void**)&qkv,  g_qkv);
    float* owin; cudaGetSymbolAddress((void**)&owin, g_owin);
    float* x1;   cudaGetSymbolAddress((void**)&x1,   g_x1);
    float* h2;   cudaGetSymbolAddress((void**)&h2,   g_h2);
    float* m1;   cudaGetSymbolAddress((void**)&m1,   g_m1);

    // 1) LN1 + window partition (zero-pad)
    ln1_gather_kernel<<<NT, 256>>>(x, n1s, n1b);

    // 2) qkv = ywin @ qkv_w + qkv_b           (19600 x 2304 x 768)
    {
        dim3 grid(C3 / 128, (NT + 127) / 128);
        sgemm128_kernel<0><<<grid, 256>>>(ywin, qkvw, qkvb, nullptr, qkv, NT, C3, C);
    }

    // 3) fused windowed attention (warp-per-query)
    attn_kernel<<<NW * HEADS * QSPLIT, 256, ATTN_SMEM_BYTES>>>(rph, rpw);

    // 4) x1 = shortcut + (owin @ proj_w + proj_b)  (scatter, crop padding)
    {
        dim3 grid(C / 128, (NT + 127) / 128);
        sgemm128_kernel<1><<<grid, 256>>>(owin, projw, projb, x, x1, NT, C, C);
    }

    // 5) LN2
    ln_rows_kernel<<<NP, 256>>>(x1, n2s, n2b, h2);

    // 6) m1 = gelu(h2 @ fc1_w + fc1_b)        (16384 x 3072 x 768)
    {
        dim3 grid(HID / 128, NP / 128);
        sgemm128_kernel<2><<<grid, 256>>>(h2, fc1w, fc1b, nullptr, m1, NP, HID, C);
    }

    // 7) out = x1 + m1 @ fc2_w + fc2_b        (16384 x 768 x 3072)
    {
        dim3 grid(C / 128, NP / 128);
        sgemm128_kernel<3><<<grid, 256>>>(m1, fc2w, fc2b, x1, out, NP, C, HID);
    }
}

// round 3
// speedup vs baseline: 2.2856x; 1.5173x over previous
#include <cuda_runtime.h>
#include <math.h>
#include <stdint.h>

// ---------------- problem constants ----------------
namespace {
constexpr int B = 4, H = 64, W = 64, C = 768;
constexpr int HEADS = 12, HD = 64, WS = 14, HID = 3072;
constexpr int NWIN = 5;               // 70/14
constexpr int NWB  = NWIN * NWIN;     // 25 windows per batch
constexpr int NW   = B * NWB;         // 100 windows
constexpr int L    = WS * WS;         // 196 tokens per window
constexpr int NT   = NW * L;          // 19600 window tokens
constexpr int NP   = B * H * W;       // 16384 real pixels
constexpr int C3   = 3 * C;           // 2304
constexpr int RELN = 2 * WS - 1;      // 27
constexpr float EPS   = 1e-6f;
constexpr float SCALE = 0.125f;       // HD^-0.5
}

// ---------------- scratch (device globals; no allocation allowed) --------
__device__ float g_ywin[(size_t)NT * C];    // LN1 output in window layout
__device__ float g_qkv [(size_t)NT * C3];   // qkv
__device__ float g_owin[(size_t)NT * C];    // attention output (window layout)
__device__ float g_x1  [(size_t)NP * C];    // shortcut + proj(o)
__device__ float g_h2  [(size_t)NP * C];    // LN2 output
__device__ float g_m1  [(size_t)NP * HID];  // gelu(fc1)

// window-row -> pixel-row index (-1 if padded)
__device__ __forceinline__ int winrow_to_pixel(int t) {
    int nw = t / L, l = t - nw * L;
    int b  = nw / NWB, r = nw - b * NWB;
    int wi = r / NWIN, wj = r - wi * NWIN;
    int i  = l / WS,   j  = l - i * WS;
    int hh = wi * WS + i, ww = wj * WS + j;
    if (hh >= H || ww >= W) return -1;
    return (b * H + hh) * W + ww;
}

__device__ __forceinline__ uint32_t f2tf32(float x) {
    uint32_t r;
    asm("cvt.rna.tf32.f32 %0, %1;" : "=r"(r) : "f"(x));
    return r;
}

__device__ __forceinline__ void mma_tf32(float c[4], const uint32_t a[4],
                                         const uint32_t b[2]) {
    asm volatile(
        "mma.sync.aligned.m16n8k8.row.col.f32.tf32.tf32.f32 "
        "{%0,%1,%2,%3}, {%4,%5,%6,%7}, {%8,%9}, {%0,%1,%2,%3};"
        : "+f"(c[0]), "+f"(c[1]), "+f"(c[2]), "+f"(c[3])
        : "r"(a[0]), "r"(a[1]), "r"(a[2]), "r"(a[3]), "r"(b[0]), "r"(b[1]));
}

// ---------------- LN1 + window gather (zero-fill padding) ----------------
__global__ void ln1_gather_kernel(const float* __restrict__ x,
                                  const float* __restrict__ sc,
                                  const float* __restrict__ bi) {
    int t = blockIdx.x;
    int tid = threadIdx.x;
    float* y = g_ywin + (size_t)t * C;
    int pix = winrow_to_pixel(t);
    if (pix < 0) {
        for (int c = tid; c < C; c += blockDim.x) y[c] = 0.f;
        return;
    }
    const float* xr = x + (size_t)pix * C;
    float s = 0.f, s2 = 0.f;
    for (int c = tid; c < C; c += blockDim.x) { float v = xr[c]; s += v; s2 += v * v; }
    __shared__ float red[64];
    for (int o = 16; o; o >>= 1) {
        s  += __shfl_xor_sync(0xffffffffu, s, o);
        s2 += __shfl_xor_sync(0xffffffffu, s2, o);
    }
    int warp = tid >> 5, lane = tid & 31;
    if (!lane) { red[warp] = s; red[32 + warp] = s2; }
    __syncthreads();
    if (tid < 32) {
        float a  = (tid < 8) ? red[tid]      : 0.f;
        float b2 = (tid < 8) ? red[32 + tid] : 0.f;
        for (int o = 4; o; o >>= 1) {
            a  += __shfl_xor_sync(0xffffffffu, a, o);
            b2 += __shfl_xor_sync(0xffffffffu, b2, o);
        }
        if (!tid) { red[0] = a; red[1] = b2; }
    }
    __syncthreads();
    float mu  = red[0] / (float)C;
    float var = red[1] / (float)C - mu * mu;
    float inv = rsqrtf(var + EPS);
    for (int c = tid; c < C; c += blockDim.x)
        y[c] = (xr[c] - mu) * inv * sc[c] + bi[c];
}

// ---------------- LN over contiguous rows (x1 -> h2) ---------------------
__global__ void ln_rows_kernel(const float* __restrict__ in,
                               const float* __restrict__ sc,
                               const float* __restrict__ bi,
                               float* __restrict__ out) {
    int t = blockIdx.x;
    int tid = threadIdx.x;
    const float* xr = in + (size_t)t * C;
    float* y = out + (size_t)t * C;
    float s = 0.f, s2 = 0.f;
    for (int c = tid; c < C; c += blockDim.x) { float v = xr[c]; s += v; s2 += v * v; }
    __shared__ float red[64];
    for (int o = 16; o; o >>= 1) {
        s  += __shfl_xor_sync(0xffffffffu, s, o);
        s2 += __shfl_xor_sync(0xffffffffu, s2, o);
    }
    int warp = tid >> 5, lane = tid & 31;
    if (!lane) { red[warp] = s; red[32 + warp] = s2; }
    __syncthreads();
    if (tid < 32) {
        float a  = (tid < 8) ? red[tid]      : 0.f;
        float b2 = (tid < 8) ? red[32 + tid] : 0.f;
        for (int o = 4; o; o >>= 1) {
            a  += __shfl_xor_sync(0xffffffffu, a, o);
            b2 += __shfl_xor_sync(0xffffffffu, b2, o);
        }
        if (!tid) { red[0] = a; red[1] = b2; }
    }
    __syncthreads();
    float mu  = red[0] / (float)C;
    float var = red[1] / (float)C - mu * mu;
    float inv = rsqrtf(var + EPS);
    for (int c = tid; c < C; c += blockDim.x)
        y[c] = (xr[c] - mu) * inv * sc[c] + bi[c];
}

// ---------------- tf32 tensor-core GEMM (mma.sync m16n8k8) ----------------
// 128x128x16 block tile, 8 warps (4m x 2n), warp tile 32x64.
// MODE 0: Cout[m,n] = acc + bias[n]                        (qkv)
// MODE 1: pixel scatter: x1[pix,n] = x[pix,n] + acc+bias   (proj + residual)
// MODE 2: Cout[m,n] = gelu(acc + bias[n])                  (fc1)
// MODE 3: Cout[m,n] = aux[m,n] + acc + bias[n]             (fc2 + residual)
template <int MODE>
__global__ void __launch_bounds__(256, 2)
tgemm_kernel(const float* __restrict__ A,
             const float* __restrict__ Bm,
             const float* __restrict__ bias,
             const float* __restrict__ aux,
             float* __restrict__ Cout,
             int M, int N, int K) {
    constexpr int BM = 128, BN = 128, BK = 16, SP = BM + 4;
    __shared__ uint32_t As[2][BK][SP];   // [k][m], tf32 bits
    __shared__ uint32_t Bs[2][BK][SP];   // [k][n], tf32 bits

    int tid  = threadIdx.x;
    int warp = tid >> 5, lane = tid & 31;
    int wm = warp >> 1, wn = warp & 1;     // 4 x 2 warp grid
    int row0 = blockIdx.y * BM, col0 = blockIdx.x * BN;
    int r = lane >> 2, cq = lane & 3;

    // gmem load mapping
    int am = tid >> 1;                      // 0..127
    int ak = (tid & 1) * 8;                 // 0 or 8
    int bn4 = (tid & 31) * 4;
    int bk0 = tid >> 5;                     // 0..7 (rows bk0, bk0+8)

    bool arow_ok = (row0 + am) < M;
    const float* Aptr = A + (size_t)(row0 + am) * K + ak;
    const float* Bptr = Bm + (size_t)bk0 * N + col0 + bn4;
    size_t bstep8 = (size_t)8 * N;

    float4 a0r, a1r, b0r, b1r;
    a0r = arow_ok ? *(const float4*)Aptr : make_float4(0, 0, 0, 0);
    a1r = arow_ok ? *(const float4*)(Aptr + 4) : make_float4(0, 0, 0, 0);
    b0r = *(const float4*)Bptr;
    b1r = *(const float4*)(Bptr + bstep8);

    auto stage = [&](int buf, float4 A0, float4 A1, float4 B0, float4 B1) {
        As[buf][ak + 0][am] = f2tf32(A0.x);
        As[buf][ak + 1][am] = f2tf32(A0.y);
        As[buf][ak + 2][am] = f2tf32(A0.z);
        As[buf][ak + 3][am] = f2tf32(A0.w);
        As[buf][ak + 4][am] = f2tf32(A1.x);
        As[buf][ak + 5][am] = f2tf32(A1.y);
        As[buf][ak + 6][am] = f2tf32(A1.z);
        As[buf][ak + 7][am] = f2tf32(A1.w);
        uint4 p0 = make_uint4(f2tf32(B0.x), f2tf32(B0.y), f2tf32(B0.z), f2tf32(B0.w));
        uint4 p1 = make_uint4(f2tf32(B1.x), f2tf32(B1.y), f2tf32(B1.z), f2tf32(B1.w));
        *(uint4*)&Bs[buf][bk0][bn4]     = p0;
        *(uint4*)&Bs[buf][bk0 + 8][bn4] = p1;
    };

    stage(0, a0r, a1r, b0r, b1r);
    __syncthreads();

    float acc[2][8][4] = {};
    int nk = K / BK;
    int buf = 0;

    for (int t = 0; t < nk; t++) {
        if (t + 1 < nk) {
            const float* Ap = Aptr + (t + 1) * BK;
            a0r = arow_ok ? *(const float4*)Ap : make_float4(0, 0, 0, 0);
            a1r = arow_ok ? *(const float4*)(Ap + 4) : make_float4(0, 0, 0, 0);
            const float* Bp = Bptr + (size_t)(t + 1) * BK * N;
            b0r = *(const float4*)Bp;
            b1r = *(const float4*)(Bp + bstep8);
        }
#pragma unroll
        for (int ks = 0; ks < 2; ks++) {
            int k0 = ks * 8;
            uint32_t af[2][4], bf[8][2];
#pragma unroll
            for (int mt = 0; mt < 2; mt++) {
                int mb = wm * 32 + mt * 16 + r;
                af[mt][0] = As[buf][k0 + cq][mb];
                af[mt][1] = As[buf][k0 + cq][mb + 8];
                af[mt][2] = As[buf][k0 + cq + 4][mb];
                af[mt][3] = As[buf][k0 + cq + 4][mb + 8];
            }
#pragma unroll
            for (int nt = 0; nt < 8; nt++) {
                int nb = wn * 64 + nt * 8 + r;
                bf[nt][0] = Bs[buf][k0 + cq][nb];
                bf[nt][1] = Bs[buf][k0 + cq + 4][nb];
            }
#pragma unroll
            for (int mt = 0; mt < 2; mt++)
#pragma unroll
                for (int nt = 0; nt < 8; nt++)
                    mma_tf32(acc[mt][nt], af[mt], bf[nt]);
        }
        if (t + 1 < nk) {
            buf ^= 1;
            stage(buf, a0r, a1r, b0r, b1r);
            __syncthreads();
        }
    }

    // epilogue: acc[mt][nt][{0,1}] -> row rA, cols cb,cb+1 ; [{2,3}] -> row rA+8
#pragma unroll
    for (int mt = 0; mt < 2; mt++) {
        int rA = row0 + wm * 32 + mt * 16 + r;
        int rB = rA + 8;
        bool okA = rA < M, okB = rB < M;
        int pixA = -1, pixB = -1;
        if (MODE == 1) {
            if (okA) pixA = winrow_to_pixel(rA);
            if (okB) pixB = winrow_to_pixel(rB);
        }
#pragma unroll
        for (int nt = 0; nt < 8; nt++) {
            int cb = col0 + wn * 64 + nt * 8 + cq * 2;
#pragma unroll
            for (int half = 0; half < 2; half++) {
                int rr = half ? rB : rA;
                bool ok = half ? okB : okA;
                if (!ok) continue;
                float v0 = acc[mt][nt][half * 2 + 0] + bias[cb];
                float v1 = acc[mt][nt][half * 2 + 1] + bias[cb + 1];
                if (MODE == 0) {
                    Cout[(size_t)rr * N + cb]     = v0;
                    Cout[(size_t)rr * N + cb + 1] = v1;
                } else if (MODE == 1) {
                    int pix = half ? pixB : pixA;
                    if (pix >= 0) {
                        Cout[(size_t)pix * N + cb]     = aux[(size_t)pix * N + cb] + v0;
                        Cout[(size_t)pix * N + cb + 1] = aux[(size_t)pix * N + cb + 1] + v1;
                    }
                } else if (MODE == 2) {
                    Cout[(size_t)rr * N + cb] =
                        0.5f * v0 * (1.f + erff(v0 * 0.70710678118654752f));
                    Cout[(size_t)rr * N + cb + 1] =
                        0.5f * v1 * (1.f + erff(v1 * 0.70710678118654752f));
                } else {
                    Cout[(size_t)rr * N + cb]     = aux[(size_t)rr * N + cb] + v0;
                    Cout[(size_t)rr * N + cb + 1] = aux[(size_t)rr * N + cb + 1] + v1;
                }
            }
        }
    }
}

// ---------------- fused attention: warp-per-query, no block barriers ------
constexpr int QSPLIT = 2;
constexpr int QPB = (L + QSPLIT - 1) / QSPLIT;   // 98
constexpr int ATTN_SMEM_FLOATS =
    L * 65 +        // Ks (padded)
    L * 64 +        // Vs
    RELN * 65 +     // RH
    RELN * 65 +     // RW
    8 * 66 +        // per-warp q
    8 * 200;        // per-warp probs
constexpr int ATTN_SMEM_BYTES = ATTN_SMEM_FLOATS * 4;

__global__ void attn_kernel(const float* __restrict__ rph,
                            const float* __restrict__ rpw) {
    extern __shared__ float sm[];
    float* Ks = sm;
    float* Vs = Ks + L * 65;
    float* RH = Vs + L * 64;
    float* RW = RH + RELN * 65;
    float* qb = RW + RELN * 65;
    float* pb = qb + 8 * 66;

    int blk = blockIdx.x;
    int part = blk & (QSPLIT - 1);
    int wh = blk / QSPLIT;
    int nw = wh / HEADS, head = wh - nw * HEADS;
    int tid = threadIdx.x;
    size_t base = (size_t)nw * L * C3 + head * HD;

    for (int idx = tid; idx < L * HD; idx += 256) {
        int l = idx >> 6, d = idx & 63;
        Ks[l * 65 + d] = g_qkv[base + (size_t)l * C3 + C + d];
        Vs[l * 64 + d] = g_qkv[base + (size_t)l * C3 + 2 * C + d];
    }
    for (int idx = tid; idx < RELN * HD; idx += 256) {
        int r = idx >> 6, d = idx & 63;
        RH[r * 65 + d] = rph[idx];
        RW[r * 65 + d] = rpw[idx];
    }
    __syncthreads();

    int warp = tid >> 5, lane = tid & 31;
    float* qv = qb + warp * 66;
    float* prob = pb + warp * 200;
    int qend = min(L, (part + 1) * QPB);

    for (int q = part * QPB + warp; q < qend; q += 8) {
        qv[lane]      = g_qkv[base + (size_t)q * C3 + lane];
        qv[32 + lane] = g_qkv[base + (size_t)q * C3 + 32 + lane];
        __syncwarp();

        int qi = q / WS, qj = q - qi * WS;

        const float* kr[7];
        const float* rh[7];
        const float* rw[7];
        bool ok[7];
        float s0[7], bh[7], bw[7];
#pragma unroll
        for (int s = 0; s < 7; s++) {
            int k = lane + 32 * s;
            ok[s] = (k < L);
            int kc = ok[s] ? k : (L - 1);
            int ki = kc / WS, kj = kc - ki * WS;
            kr[s] = Ks + kc * 65;
            rh[s] = RH + (qi - ki + WS - 1) * 65;
            rw[s] = RW + (qj - kj + WS - 1) * 65;
            s0[s] = 0.f; bh[s] = 0.f; bw[s] = 0.f;
        }
#pragma unroll 8
        for (int d = 0; d < HD; d++) {
            float qd = qv[d];
#pragma unroll
            for (int s = 0; s < 7; s++) {
                s0[s] = fmaf(qd, kr[s][d], s0[s]);
                bh[s] = fmaf(qd, rh[s][d], bh[s]);
                bw[s] = fmaf(qd, rw[s][d], bw[s]);
            }
        }
        float lt[7];
#pragma unroll
        for (int s = 0; s < 7; s++)
            lt[s] = ok[s] ? (s0[s] * SCALE + bh[s] + bw[s]) : -1e30f;

        float mx = lt[0];
#pragma unroll
        for (int s = 1; s < 7; s++) mx = fmaxf(mx, lt[s]);
        for (int o = 16; o; o >>= 1) mx = fmaxf(mx, __shfl_xor_sync(0xffffffffu, mx, o));
        float sum = 0.f;
#pragma unroll
        for (int s = 0; s < 7; s++) { lt[s] = expf(lt[s] - mx); sum += lt[s]; }
        for (int o = 16; o; o >>= 1) sum += __shfl_xor_sync(0xffffffffu, sum, o);
        float inv = 1.f / sum;
#pragma unroll
        for (int s = 0; s < 7; s++) {
            int k = lane + 32 * s;
            if (k < L) prob[k] = lt[s] * inv;
        }
        __syncwarp();

        int d0 = lane * 2;
        float ax = 0.f, ay = 0.f;
#pragma unroll 4
        for (int k = 0; k < L; k++) {
            float p = prob[k];
            float2 v = *(const float2*)&Vs[k * 64 + d0];
            ax = fmaf(p, v.x, ax);
            ay = fmaf(p, v.y, ay);
        }
        float2 o2 = make_float2(ax, ay);
        *(float2*)&g_owin[((size_t)nw * L + q) * C + head * HD + d0] = o2;
        __syncwarp();
    }
}

// ---------------- launch ---------------------------------------------------
extern "C" void kernel_launch(void* const* d_in, const int* in_sizes, int n_in,
                              void* d_out, int out_size) {
    const float* x      = (const float*)d_in[0];
    const float* n1s    = (const float*)d_in[1];
    const float* n1b    = (const float*)d_in[2];
    const float* qkvw   = (const float*)d_in[3];
    const float* qkvb   = (const float*)d_in[4];
    const float* rph    = (const float*)d_in[5];
    const float* rpw    = (const float*)d_in[6];
    const float* projw  = (const float*)d_in[7];
    const float* projb  = (const float*)d_in[8];
    const float* n2s    = (const float*)d_in[9];
    const float* n2b    = (const float*)d_in[10];
    const float* fc1w   = (const float*)d_in[11];
    const float* fc1b   = (const float*)d_in[12];
    const float* fc2w   = (const float*)d_in[13];
    const float* fc2b   = (const float*)d_in[14];
    float* out = (float*)d_out;

    cudaFuncSetAttribute(attn_kernel, cudaFuncAttributeMaxDynamicSharedMemorySize,
                         ATTN_SMEM_BYTES);

    float* ywin; cudaGetSymbolAddress((void**)&ywin, g_ywin);
    float* qkv;  cudaGetSymbolAddress((void**)&qkv,  g_qkv);
    float* owin; cudaGetSymbolAddress((void**)&owin, g_owin);
    float* x1;   cudaGetSymbolAddress((void**)&x1,   g_x1);
    float* h2;   cudaGetSymbolAddress((void**)&h2,   g_h2);
    float* m1;   cudaGetSymbolAddress((void**)&m1,   g_m1);

    // 1) LN1 + window partition (zero-pad)
    ln1_gather_kernel<<<NT, 256>>>(x, n1s, n1b);

    // 2) qkv = ywin @ qkv_w + qkv_b           (19600 x 2304 x 768)
    {
        dim3 grid(C3 / 128, (NT + 127) / 128);
        tgemm_kernel<0><<<grid, 256>>>(ywin, qkvw, qkvb, nullptr, qkv, NT, C3, C);
    }

    // 3) fused windowed attention (warp-per-query)
    attn_kernel<<<NW * HEADS * QSPLIT, 256, ATTN_SMEM_BYTES>>>(rph, rpw);

    // 4) x1 = shortcut + (owin @ proj_w + proj_b)  (scatter, crop padding)
    {
        dim3 grid(C / 128, (NT + 127) / 128);
        tgemm_kernel<1><<<grid, 256>>>(owin, projw, projb, x, x1, NT, C, C);
    }

    // 5) LN2
    ln_rows_kernel<<<NP, 256>>>(x1, n2s, n2b, h2);

    // 6) m1 = gelu(h2 @ fc1_w + fc1_b)        (16384 x 3072 x 768)
    {
        dim3 grid(HID / 128, NP / 128);
        tgemm_kernel<2><<<grid, 256>>>(h2, fc1w, fc1b, nullptr, m1, NP, HID, C);
    }

    // 7) out = x1 + m1 @ fc2_w + fc2_b        (16384 x 768 x 3072)
    {
        dim3 grid(C / 128, NP / 128);
        tgemm_kernel<3><<<grid, 256>>>(m1, fc2w, fc2b, x1, out, NP, C, HID);
    }
}

// round 4
// speedup vs baseline: 2.4932x; 1.0908x over previous
#include <cuda_runtime.h>
#include <math.h>
#include <stdint.h>

// ---------------- problem constants ----------------
namespace {
constexpr int B = 4, H = 64, W = 64, C = 768;
constexpr int HEADS = 12, HD = 64, WS = 14, HID = 3072;
constexpr int NWIN = 5;               // 70/14
constexpr int NWB  = NWIN * NWIN;     // 25 windows per batch
constexpr int NW   = B * NWB;         // 100 windows
constexpr int L    = WS * WS;         // 196 tokens per window
constexpr int NT   = NW * L;          // 19600 window tokens
constexpr int NP   = B * H * W;       // 16384 real pixels
constexpr int C3   = 3 * C;           // 2304
constexpr int RELN = 2 * WS - 1;      // 27
constexpr float EPS   = 1e-6f;
constexpr float SCALE = 0.125f;       // HD^-0.5
}

// ---------------- scratch (device globals; no allocation allowed) --------
__device__ float g_ywin[(size_t)NT * C];    // LN1 output in window layout
__device__ float g_qkv [(size_t)NT * C3];   // qkv
__device__ float g_owin[(size_t)NT * C];    // attention output (window layout)
__device__ float g_x1  [(size_t)NP * C];    // shortcut + proj(o)
__device__ float g_h2  [(size_t)NP * C];    // LN2 output
__device__ float g_m1  [(size_t)NP * HID];  // gelu(fc1)

// window-row -> pixel-row index (-1 if padded)
__device__ __forceinline__ int winrow_to_pixel(int t) {
    int nw = t / L, l = t - nw * L;
    int b  = nw / NWB, r = nw - b * NWB;
    int wi = r / NWIN, wj = r - wi * NWIN;
    int i  = l / WS,   j  = l - i * WS;
    int hh = wi * WS + i, ww = wj * WS + j;
    if (hh >= H || ww >= W) return -1;
    return (b * H + hh) * W + ww;
}

__device__ __forceinline__ uint32_t f2tf32(float x) {
    uint32_t r;
    asm("cvt.rna.tf32.f32 %0, %1;" : "=r"(r) : "f"(x));
    return r;
}

__device__ __forceinline__ void mma_tf32(float c[4], const uint32_t a[4],
                                         const uint32_t b[2]) {
    asm volatile(
        "mma.sync.aligned.m16n8k8.row.col.f32.tf32.tf32.f32 "
        "{%0,%1,%2,%3}, {%4,%5,%6,%7}, {%8,%9}, {%0,%1,%2,%3};"
        : "+f"(c[0]), "+f"(c[1]), "+f"(c[2]), "+f"(c[3])
        : "r"(a[0]), "r"(a[1]), "r"(a[2]), "r"(a[3]), "r"(b[0]), "r"(b[1]));
}

// ---------------- LN1 + window gather (zero-fill padding) ----------------
__global__ void ln1_gather_kernel(const float* __restrict__ x,
                                  const float* __restrict__ sc,
                                  const float* __restrict__ bi) {
    int t = blockIdx.x;
    int tid = threadIdx.x;
    float* y = g_ywin + (size_t)t * C;
    int pix = winrow_to_pixel(t);
    if (pix < 0) {
        for (int c = tid; c < C; c += blockDim.x) y[c] = 0.f;
        return;
    }
    const float* xr = x + (size_t)pix * C;
    float s = 0.f, s2 = 0.f;
    for (int c = tid; c < C; c += blockDim.x) { float v = xr[c]; s += v; s2 += v * v; }
    __shared__ float red[64];
    for (int o = 16; o; o >>= 1) {
        s  += __shfl_xor_sync(0xffffffffu, s, o);
        s2 += __shfl_xor_sync(0xffffffffu, s2, o);
    }
    int warp = tid >> 5, lane = tid & 31;
    if (!lane) { red[warp] = s; red[32 + warp] = s2; }
    __syncthreads();
    if (tid < 32) {
        float a  = (tid < 8) ? red[tid]      : 0.f;
        float b2 = (tid < 8) ? red[32 + tid] : 0.f;
        for (int o = 4; o; o >>= 1) {
            a  += __shfl_xor_sync(0xffffffffu, a, o);
            b2 += __shfl_xor_sync(0xffffffffu, b2, o);
        }
        if (!tid) { red[0] = a; red[1] = b2; }
    }
    __syncthreads();
    float mu  = red[0] / (float)C;
    float var = red[1] / (float)C - mu * mu;
    float inv = rsqrtf(var + EPS);
    for (int c = tid; c < C; c += blockDim.x)
        y[c] = (xr[c] - mu) * inv * sc[c] + bi[c];
}

// ---------------- LN over contiguous rows (x1 -> h2) ---------------------
__global__ void ln_rows_kernel(const float* __restrict__ in,
                               const float* __restrict__ sc,
                               const float* __restrict__ bi,
                               float* __restrict__ out) {
    int t = blockIdx.x;
    int tid = threadIdx.x;
    const float* xr = in + (size_t)t * C;
    float* y = out + (size_t)t * C;
    float s = 0.f, s2 = 0.f;
    for (int c = tid; c < C; c += blockDim.x) { float v = xr[c]; s += v; s2 += v * v; }
    __shared__ float red[64];
    for (int o = 16; o; o >>= 1) {
        s  += __shfl_xor_sync(0xffffffffu, s, o);
        s2 += __shfl_xor_sync(0xffffffffu, s2, o);
    }
    int warp = tid >> 5, lane = tid & 31;
    if (!lane) { red[warp] = s; red[32 + warp] = s2; }
    __syncthreads();
    if (tid < 32) {
        float a  = (tid < 8) ? red[tid]      : 0.f;
        float b2 = (tid < 8) ? red[32 + tid] : 0.f;
        for (int o = 4; o; o >>= 1) {
            a  += __shfl_xor_sync(0xffffffffu, a, o);
            b2 += __shfl_xor_sync(0xffffffffu, b2, o);
        }
        if (!tid) { red[0] = a; red[1] = b2; }
    }
    __syncthreads();
    float mu  = red[0] / (float)C;
    float var = red[1] / (float)C - mu * mu;
    float inv = rsqrtf(var + EPS);
    for (int c = tid; c < C; c += blockDim.x)
        y[c] = (xr[c] - mu) * inv * sc[c] + bi[c];
}

// ---------------- tf32 tensor-core GEMM (mma.sync m16n8k8) ----------------
// 128x128x16 block tile, 8 warps (4m x 2n), warp tile 32x64.
// Conflict-free smem: stride SP=136 (== 8 mod 32) makes fragment loads
// bank-bijective; A staged by (m = tid&127, kb = (tid>>7)*8) so STS
// wavefronts are 32 consecutive floats.
template <int MODE>
__global__ void __launch_bounds__(256, 2)
tgemm_kernel(const float* __restrict__ A,
             const float* __restrict__ Bm,
             const float* __restrict__ bias,
             const float* __restrict__ aux,
             float* __restrict__ Cout,
             int M, int N, int K) {
    constexpr int BM = 128, BN = 128, BK = 16, SP = 136;
    __shared__ uint32_t As[2][BK][SP];   // [k][m], tf32 bits
    __shared__ uint32_t Bs[2][BK][SP];   // [k][n], tf32 bits

    int tid  = threadIdx.x;
    int warp = tid >> 5, lane = tid & 31;
    int wm = warp >> 1, wn = warp & 1;     // 4 x 2 warp grid
    int row0 = blockIdx.y * BM, col0 = blockIdx.x * BN;
    int r = lane >> 2, cq = lane & 3;

    // gmem load mapping (conflict-free STS)
    int am = tid & 127;                    // 0..127
    int akb = (tid >> 7) * 8;              // 0 or 8
    int bn4 = (tid & 31) * 4;
    int bk0 = tid >> 5;                    // 0..7 (rows bk0, bk0+8)

    bool arow_ok = (row0 + am) < M;
    const float* Aptr = A + (size_t)(row0 + am) * K + akb;
    const float* Bptr = Bm + (size_t)bk0 * N + col0 + bn4;
    size_t bstep8 = (size_t)8 * N;

    float4 a0r, a1r, b0r, b1r;
    a0r = arow_ok ? *(const float4*)Aptr : make_float4(0, 0, 0, 0);
    a1r = arow_ok ? *(const float4*)(Aptr + 4) : make_float4(0, 0, 0, 0);
    b0r = *(const float4*)Bptr;
    b1r = *(const float4*)(Bptr + bstep8);

    auto stage = [&](int buf, float4 A0, float4 A1, float4 B0, float4 B1) {
        As[buf][akb + 0][am] = f2tf32(A0.x);
        As[buf][akb + 1][am] = f2tf32(A0.y);
        As[buf][akb + 2][am] = f2tf32(A0.z);
        As[buf][akb + 3][am] = f2tf32(A0.w);
        As[buf][akb + 4][am] = f2tf32(A1.x);
        As[buf][akb + 5][am] = f2tf32(A1.y);
        As[buf][akb + 6][am] = f2tf32(A1.z);
        As[buf][akb + 7][am] = f2tf32(A1.w);
        uint4 p0 = make_uint4(f2tf32(B0.x), f2tf32(B0.y), f2tf32(B0.z), f2tf32(B0.w));
        uint4 p1 = make_uint4(f2tf32(B1.x), f2tf32(B1.y), f2tf32(B1.z), f2tf32(B1.w));
        *(uint4*)&Bs[buf][bk0][bn4]     = p0;
        *(uint4*)&Bs[buf][bk0 + 8][bn4] = p1;
    };

    stage(0, a0r, a1r, b0r, b1r);
    __syncthreads();

    float acc[2][8][4] = {};
    int nk = K / BK;
    int buf = 0;

    for (int t = 0; t < nk; t++) {
        if (t + 1 < nk) {
            const float* Ap = Aptr + (t + 1) * BK;
            a0r = arow_ok ? *(const float4*)Ap : make_float4(0, 0, 0, 0);
            a1r = arow_ok ? *(const float4*)(Ap + 4) : make_float4(0, 0, 0, 0);
            const float* Bp = Bptr + (size_t)(t + 1) * BK * N;
            b0r = *(const float4*)Bp;
            b1r = *(const float4*)(Bp + bstep8);
        }
#pragma unroll
        for (int ks = 0; ks < 2; ks++) {
            int k0 = ks * 8;
            uint32_t af[2][4], bf[8][2];
#pragma unroll
            for (int mt = 0; mt < 2; mt++) {
                int mb = wm * 32 + mt * 16 + r;
                af[mt][0] = As[buf][k0 + cq][mb];
                af[mt][1] = As[buf][k0 + cq][mb + 8];
                af[mt][2] = As[buf][k0 + cq + 4][mb];
                af[mt][3] = As[buf][k0 + cq + 4][mb + 8];
            }
#pragma unroll
            for (int nt = 0; nt < 8; nt++) {
                int nb = wn * 64 + nt * 8 + r;
                bf[nt][0] = Bs[buf][k0 + cq][nb];
                bf[nt][1] = Bs[buf][k0 + cq + 4][nb];
            }
#pragma unroll
            for (int mt = 0; mt < 2; mt++)
#pragma unroll
                for (int nt = 0; nt < 8; nt++)
                    mma_tf32(acc[mt][nt], af[mt], bf[nt]);
        }
        if (t + 1 < nk) {
            buf ^= 1;
            stage(buf, a0r, a1r, b0r, b1r);
            __syncthreads();
        }
    }

    // epilogue
#pragma unroll
    for (int mt = 0; mt < 2; mt++) {
        int rA = row0 + wm * 32 + mt * 16 + r;
        int rB = rA + 8;
        bool okA = rA < M, okB = rB < M;
        int pixA = -1, pixB = -1;
        if (MODE == 1) {
            if (okA) pixA = winrow_to_pixel(rA);
            if (okB) pixB = winrow_to_pixel(rB);
        }
#pragma unroll
        for (int nt = 0; nt < 8; nt++) {
            int cb = col0 + wn * 64 + nt * 8 + cq * 2;
#pragma unroll
            for (int half = 0; half < 2; half++) {
                int rr = half ? rB : rA;
                bool ok = half ? okB : okA;
                if (!ok) continue;
                float v0 = acc[mt][nt][half * 2 + 0] + bias[cb];
                float v1 = acc[mt][nt][half * 2 + 1] + bias[cb + 1];
                if (MODE == 0) {
                    Cout[(size_t)rr * N + cb]     = v0;
                    Cout[(size_t)rr * N + cb + 1] = v1;
                } else if (MODE == 1) {
                    int pix = half ? pixB : pixA;
                    if (pix >= 0) {
                        Cout[(size_t)pix * N + cb]     = aux[(size_t)pix * N + cb] + v0;
                        Cout[(size_t)pix * N + cb + 1] = aux[(size_t)pix * N + cb + 1] + v1;
                    }
                } else if (MODE == 2) {
                    Cout[(size_t)rr * N + cb] =
                        0.5f * v0 * (1.f + erff(v0 * 0.70710678118654752f));
                    Cout[(size_t)rr * N + cb + 1] =
                        0.5f * v1 * (1.f + erff(v1 * 0.70710678118654752f));
                } else {
                    Cout[(size_t)rr * N + cb]     = aux[(size_t)rr * N + cb] + v0;
                    Cout[(size_t)rr * N + cb + 1] = aux[(size_t)rr * N + cb + 1] + v1;
                }
            }
        }
    }
}

// ---------------- fused attention: warp-per-query-PAIR --------------------
// Two same-row queries per warp iteration: K rows and RH rows are loaded
// once and shared between the pair (smem-wavefront bound -> ~1.5x less LDS).
constexpr int QSPLIT = 2;
constexpr int QPB = L / QSPLIT;   // 98 (even)
constexpr int ATTN_SMEM_FLOATS =
    L * 65 +        // Ks (padded)
    L * 64 +        // Vs
    RELN * 65 +     // RH
    RELN * 65 +     // RW
    8 * 132 +       // per-warp q pair (2 x 66)
    8 * 400;        // per-warp probs (2 x 200)
constexpr int ATTN_SMEM_BYTES = ATTN_SMEM_FLOATS * 4;

__global__ void attn_kernel(const float* __restrict__ rph,
                            const float* __restrict__ rpw) {
    extern __shared__ float sm[];
    float* Ks = sm;
    float* Vs = Ks + L * 65;
    float* RH = Vs + L * 64;
    float* RW = RH + RELN * 65;
    float* qb = RW + RELN * 65;
    float* pb = qb + 8 * 132;

    int blk = blockIdx.x;
    int part = blk & (QSPLIT - 1);
    int wh = blk / QSPLIT;
    int nw = wh / HEADS, head = wh - nw * HEADS;
    int tid = threadIdx.x;
    size_t base = (size_t)nw * L * C3 + head * HD;

    for (int idx = tid; idx < L * HD; idx += 256) {
        int l = idx >> 6, d = idx & 63;
        Ks[l * 65 + d] = g_qkv[base + (size_t)l * C3 + C + d];
        Vs[l * 64 + d] = g_qkv[base + (size_t)l * C3 + 2 * C + d];
    }
    for (int idx = tid; idx < RELN * HD; idx += 256) {
        int r = idx >> 6, d = idx & 63;
        RH[r * 65 + d] = rph[idx];
        RW[r * 65 + d] = rpw[idx];
    }
    __syncthreads();

    int warp = tid >> 5, lane = tid & 31;
    float* qv0 = qb + warp * 132;
    float* qv1 = qv0 + 66;
    float* prob0 = pb + warp * 400;
    float* prob1 = prob0 + 200;
    int qend = (part + 1) * QPB;

    for (int q0 = part * QPB + warp * 2; q0 < qend; q0 += 16) {
        int q1 = q0 + 1;
        { // load both query vectors (64 floats each)
            float2 a = *(const float2*)&g_qkv[base + (size_t)q0 * C3 + lane * 2];
            float2 b = *(const float2*)&g_qkv[base + (size_t)q1 * C3 + lane * 2];
            *(float2*)&qv0[lane * 2] = a;
            *(float2*)&qv1[lane * 2] = b;
        }
        __syncwarp();

        int qi = q0 / WS, qj0 = q0 - qi * WS, qj1 = qj0 + 1;  // same row

        int koff[7], hoff[7], w0off[7], w1off[7];
        bool ok[7];
        float sA[7], sB[7], bhA[7], bhB[7], bwA[7], bwB[7];
#pragma unroll
        for (int s = 0; s < 7; s++) {
            int k = lane + 32 * s;
            ok[s] = (k < L);
            int kc = ok[s] ? k : (L - 1);
            int ki = kc / WS, kj = kc - ki * WS;
            koff[s]  = kc * 65;
            hoff[s]  = (qi - ki + WS - 1) * 65;
            w0off[s] = (qj0 - kj + WS - 1) * 65;
            w1off[s] = (qj1 - kj + WS - 1) * 65;
            sA[s] = 0.f; sB[s] = 0.f;
            bhA[s] = 0.f; bhB[s] = 0.f;
            bwA[s] = 0.f; bwB[s] = 0.f;
        }
#pragma unroll 4
        for (int d = 0; d < HD; d++) {
            float qa = qv0[d], qc = qv1[d];
#pragma unroll
            for (int s = 0; s < 7; s++) {
                float kv = Ks[koff[s] + d];
                float hv = RH[hoff[s] + d];
                sA[s]  = fmaf(qa, kv, sA[s]);
                sB[s]  = fmaf(qc, kv, sB[s]);
                bhA[s] = fmaf(qa, hv, bhA[s]);
                bhB[s] = fmaf(qc, hv, bhB[s]);
                bwA[s] = fmaf(qa, RW[w0off[s] + d], bwA[s]);
                bwB[s] = fmaf(qc, RW[w1off[s] + d], bwB[s]);
            }
        }
        float ltA[7], ltB[7];
#pragma unroll
        for (int s = 0; s < 7; s++) {
            ltA[s] = ok[s] ? (sA[s] * SCALE + bhA[s] + bwA[s]) : -1e30f;
            ltB[s] = ok[s] ? (sB[s] * SCALE + bhB[s] + bwB[s]) : -1e30f;
        }

        // softmax for both queries
        float mxA = ltA[0], mxB = ltB[0];
#pragma unroll
        for (int s = 1; s < 7; s++) { mxA = fmaxf(mxA, ltA[s]); mxB = fmaxf(mxB, ltB[s]); }
        for (int o = 16; o; o >>= 1) {
            mxA = fmaxf(mxA, __shfl_xor_sync(0xffffffffu, mxA, o));
            mxB = fmaxf(mxB, __shfl_xor_sync(0xffffffffu, mxB, o));
        }
        float smA = 0.f, smB = 0.f;
#pragma unroll
        for (int s = 0; s < 7; s++) {
            ltA[s] = expf(ltA[s] - mxA); smA += ltA[s];
            ltB[s] = expf(ltB[s] - mxB); smB += ltB[s];
        }
        for (int o = 16; o; o >>= 1) {
            smA += __shfl_xor_sync(0xffffffffu, smA, o);
            smB += __shfl_xor_sync(0xffffffffu, smB, o);
        }
        float ivA = 1.f / smA, ivB = 1.f / smB;
#pragma unroll
        for (int s = 0; s < 7; s++) {
            int k = lane + 32 * s;
            if (k < L) { prob0[k] = ltA[s] * ivA; prob1[k] = ltB[s] * ivB; }
        }
        __syncwarp();

        // AV for both queries; V row loaded once
        int d0 = lane * 2;
        float a0 = 0.f, a1 = 0.f, b0 = 0.f, b1 = 0.f;
#pragma unroll 4
        for (int k = 0; k < L; k++) {
            float2 v = *(const float2*)&Vs[k * 64 + d0];
            float pA = prob0[k], pB = prob1[k];
            a0 = fmaf(pA, v.x, a0);
            a1 = fmaf(pA, v.y, a1);
            b0 = fmaf(pB, v.x, b0);
            b1 = fmaf(pB, v.y, b1);
        }
        size_t orow = ((size_t)nw * L + q0) * C + head * HD + d0;
        *(float2*)&g_owin[orow]     = make_float2(a0, a1);
        *(float2*)&g_owin[orow + C] = make_float2(b0, b1);
        __syncwarp();
    }
}

// ---------------- launch ---------------------------------------------------
extern "C" void kernel_launch(void* const* d_in, const int* in_sizes, int n_in,
                              void* d_out, int out_size) {
    const float* x      = (const float*)d_in[0];
    const float* n1s    = (const float*)d_in[1];
    const float* n1b    = (const float*)d_in[2];
    const float* qkvw   = (const float*)d_in[3];
    const float* qkvb   = (const float*)d_in[4];
    const float* rph    = (const float*)d_in[5];
    const float* rpw    = (const float*)d_in[6];
    const float* projw  = (const float*)d_in[7];
    const float* projb  = (const float*)d_in[8];
    const float* n2s    = (const float*)d_in[9];
    const float* n2b    = (const float*)d_in[10];
    const float* fc1w   = (const float*)d_in[11];
    const float* fc1b   = (const float*)d_in[12];
    const float* fc2w   = (const float*)d_in[13];
    const float* fc2b   = (const float*)d_in[14];
    float* out = (float*)d_out;

    cudaFuncSetAttribute(attn_kernel, cudaFuncAttributeMaxDynamicSharedMemorySize,
                         ATTN_SMEM_BYTES);

    float* ywin; cudaGetSymbolAddress((void**)&ywin, g_ywin);
    float* qkv;  cudaGetSymbolAddress((void**)&qkv,  g_qkv);
    float* owin; cudaGetSymbolAddress((void**)&owin, g_owin);
    float* x1;   cudaGetSymbolAddress((void**)&x1,   g_x1);
    float* h2;   cudaGetSymbolAddress((void**)&h2,   g_h2);
    float* m1;   cudaGetSymbolAddress((void**)&m1,   g_m1);

    // 1) LN1 + window partition (zero-pad)
    ln1_gather_kernel<<<NT, 256>>>(x, n1s, n1b);

    // 2) qkv = ywin @ qkv_w + qkv_b           (19600 x 2304 x 768)
    {
        dim3 grid(C3 / 128, (NT + 127) / 128);
        tgemm_kernel<0><<<grid, 256>>>(ywin, qkvw, qkvb, nullptr, qkv, NT, C3, C);
    }

    // 3) fused windowed attention (warp-per-query-pair)
    attn_kernel<<<NW * HEADS * QSPLIT, 256, ATTN_SMEM_BYTES>>>(rph, rpw);

    // 4) x1 = shortcut + (owin @ proj_w + proj_b)  (scatter, crop padding)
    {
        dim3 grid(C / 128, (NT + 127) / 128);
        tgemm_kernel<1><<<grid, 256>>>(owin, projw, projb, x, x1, NT, C, C);
    }

    // 5) LN2
    ln_rows_kernel<<<NP, 256>>>(x1, n2s, n2b, h2);

    // 6) m1 = gelu(h2 @ fc1_w + fc1_b)        (16384 x 3072 x 768)
    {
        dim3 grid(HID / 128, NP / 128);
        tgemm_kernel<2><<<grid, 256>>>(h2, fc1w, fc1b, nullptr, m1, NP, HID, C);
    }

    // 7) out = x1 + m1 @ fc2_w + fc2_b        (16384 x 768 x 3072)
    {
        dim3 grid(C / 128, NP / 128);
        tgemm_kernel<3><<<grid, 256>>>(m1, fc2w, fc2b, x1, out, NP, C, HID);
    }
}

// round 5
// speedup vs baseline: 3.7401x; 1.5001x over previous
#include <cuda_runtime.h>
#include <cuda_fp16.h>
#include <math.h>
#include <stdint.h>

// ---------------- problem constants ----------------
namespace {
constexpr int B = 4, H = 64, W = 64, C = 768;
constexpr int HEADS = 12, HD = 64, WS = 14, HID = 3072;
constexpr int NWIN = 5;               // 70/14
constexpr int NWB  = NWIN * NWIN;     // 25 windows per batch
constexpr int NW   = B * NWB;         // 100 windows
constexpr int L    = WS * WS;         // 196 tokens per window
constexpr int NT   = NW * L;          // 19600 window tokens
constexpr int NP   = B * H * W;       // 16384 real pixels
constexpr int C3   = 3 * C;           // 2304
constexpr int RELN = 2 * WS - 1;      // 27
constexpr float EPS   = 1e-6f;
constexpr float SCALE = 0.125f;       // HD^-0.5
}

// ---------------- scratch (device globals; no allocation allowed) --------
__device__ __half g_ywin_h[(size_t)NT * C];    // LN1 out (window layout, fp16)
__device__ float  g_qkv  [(size_t)NT * C3];    // qkv (fp32, attention input)
__device__ __half g_owin_h[(size_t)NT * C];    // attention out (fp16)
__device__ float  g_x1   [(size_t)NP * C];     // shortcut + proj(o)
__device__ __half g_h2_h [(size_t)NP * C];     // LN2 out (fp16)
__device__ __half g_m1_h [(size_t)NP * HID];   // gelu(fc1) (fp16)
// fp16 weight copies
__device__ __half g_qkvw_h[(size_t)C * C3];
__device__ __half g_projw_h[(size_t)C * C];
__device__ __half g_fc1w_h[(size_t)C * HID];
__device__ __half g_fc2w_h[(size_t)HID * C];

// window-row -> pixel-row index (-1 if padded)
__device__ __forceinline__ int winrow_to_pixel(int t) {
    int nw = t / L, l = t - nw * L;
    int b  = nw / NWB, r = nw - b * NWB;
    int wi = r / NWIN, wj = r - wi * NWIN;
    int i  = l / WS,   j  = l - i * WS;
    int hh = wi * WS + i, ww = wj * WS + j;
    if (hh >= H || ww >= W) return -1;
    return (b * H + hh) * W + ww;
}

__device__ __forceinline__ void mma_f16(float c[4], const uint32_t a[4],
                                        const uint32_t b[2]) {
    asm volatile(
        "mma.sync.aligned.m16n8k16.row.col.f32.f16.f16.f32 "
        "{%0,%1,%2,%3}, {%4,%5,%6,%7}, {%8,%9}, {%0,%1,%2,%3};"
        : "+f"(c[0]), "+f"(c[1]), "+f"(c[2]), "+f"(c[3])
        : "r"(a[0]), "r"(a[1]), "r"(a[2]), "r"(a[3]), "r"(b[0]), "r"(b[1]));
}

// ---------------- weight fp32 -> fp16 --------------------------------------
__global__ void f2h_kernel(const float* __restrict__ src,
                           __half* __restrict__ dst, int n2) {
    int i = blockIdx.x * blockDim.x + threadIdx.x;
    int stride = gridDim.x * blockDim.x;
    for (; i < n2; i += stride) {
        float2 v = ((const float2*)src)[i];
        ((half2*)dst)[i] = __floats2half2_rn(v.x, v.y);
    }
}

// ---------------- LN1 + window gather (fp16 out, zero-fill padding) -------
__global__ void ln1_gather_kernel(const float* __restrict__ x,
                                  const float* __restrict__ sc,
                                  const float* __restrict__ bi) {
    int t = blockIdx.x;
    int tid = threadIdx.x;
    __half* y = g_ywin_h + (size_t)t * C;
    int pix = winrow_to_pixel(t);
    if (pix < 0) {
        for (int c = tid; c < C; c += blockDim.x) y[c] = __float2half(0.f);
        return;
    }
    const float* xr = x + (size_t)pix * C;
    float s = 0.f, s2 = 0.f;
    for (int c = tid; c < C; c += blockDim.x) { float v = xr[c]; s += v; s2 += v * v; }
    __shared__ float red[64];
    for (int o = 16; o; o >>= 1) {
        s  += __shfl_xor_sync(0xffffffffu, s, o);
        s2 += __shfl_xor_sync(0xffffffffu, s2, o);
    }
    int warp = tid >> 5, lane = tid & 31;
    if (!lane) { red[warp] = s; red[32 + warp] = s2; }
    __syncthreads();
    if (tid < 32) {
        float a  = (tid < 8) ? red[tid]      : 0.f;
        float b2 = (tid < 8) ? red[32 + tid] : 0.f;
        for (int o = 4; o; o >>= 1) {
            a  += __shfl_xor_sync(0xffffffffu, a, o);
            b2 += __shfl_xor_sync(0xffffffffu, b2, o);
        }
        if (!tid) { red[0] = a; red[1] = b2; }
    }
    __syncthreads();
    float mu  = red[0] / (float)C;
    float var = red[1] / (float)C - mu * mu;
    float inv = rsqrtf(var + EPS);
    for (int c = tid; c < C; c += blockDim.x)
        y[c] = __float2half((xr[c] - mu) * inv * sc[c] + bi[c]);
}

// ---------------- LN over contiguous rows (x1 -> h2 fp16) -----------------
__global__ void ln_rows_kernel(const float* __restrict__ in,
                               const float* __restrict__ sc,
                               const float* __restrict__ bi) {
    int t = blockIdx.x;
    int tid = threadIdx.x;
    const float* xr = in + (size_t)t * C;
    __half* y = g_h2_h + (size_t)t * C;
    float s = 0.f, s2 = 0.f;
    for (int c = tid; c < C; c += blockDim.x) { float v = xr[c]; s += v; s2 += v * v; }
    __shared__ float red[64];
    for (int o = 16; o; o >>= 1) {
        s  += __shfl_xor_sync(0xffffffffu, s, o);
        s2 += __shfl_xor_sync(0xffffffffu, s2, o);
    }
    int warp = tid >> 5, lane = tid & 31;
    if (!lane) { red[warp] = s; red[32 + warp] = s2; }
    __syncthreads();
    if (tid < 32) {
        float a  = (tid < 8) ? red[tid]      : 0.f;
        float b2 = (tid < 8) ? red[32 + tid] : 0.f;
        for (int o = 4; o; o >>= 1) {
            a  += __shfl_xor_sync(0xffffffffu, a, o);
            b2 += __shfl_xor_sync(0xffffffffu, b2, o);
        }
        if (!tid) { red[0] = a; red[1] = b2; }
    }
    __syncthreads();
    float mu  = red[0] / (float)C;
    float var = red[1] / (float)C - mu * mu;
    float inv = rsqrtf(var + EPS);
    for (int c = tid; c < C; c += blockDim.x)
        y[c] = __float2half((xr[c] - mu) * inv * sc[c] + bi[c]);
}

// ---------------- fp16 tensor-core GEMM (mma.sync m16n8k16) ---------------
// 128x128x16 block tile, 8 warps (4m x 2n), warp tile 32x64.
// Smem: half2-packed (k,k+1) pairs, stride 136 (conflict-free).
// MODE 0: g_qkv[m,n] (fp32) = acc + bias[n]
// MODE 1: pixel scatter: x1[pix,n] (fp32) = x[pix,n] + acc + bias
// MODE 2: m1[m,n] (fp16)  = gelu(acc + bias[n])
// MODE 3: out[m,n] (fp32) = aux[m,n] + acc + bias[n]
template <int MODE>
__global__ void __launch_bounds__(256, 2)
hgemm_kernel(const __half* __restrict__ A,
             const __half* __restrict__ Bh,
             const float* __restrict__ bias,
             const float* __restrict__ aux,
             void* __restrict__ CoutV,
             int M, int N, int K) {
    constexpr int SP = 136;
    __shared__ uint32_t As[2][8][SP];   // [k2][m] half2(k even, k odd)
    __shared__ uint32_t Bs[2][8][SP];   // [k2][n]
    float*  Cf = (float*)CoutV;
    __half* Ch = (__half*)CoutV;

    int tid  = threadIdx.x;
    int warp = tid >> 5, lane = tid & 31;
    int wm = warp >> 1, wn = warp & 1;     // 4 x 2 warp grid
    int row0 = blockIdx.y * 128, col0 = blockIdx.x * 128;
    int r = lane >> 2, cq = lane & 3;

    // staging maps
    int am  = tid & 127;
    int ak2 = (tid >> 7) * 4;            // k2 base: 0 or 4
    int akh = ak2 * 2;                   // half offset: 0 or 8
    int bn4 = (tid & 31) * 4;
    int bq  = tid >> 5;                  // k2 row 0..7 (k rows 2bq, 2bq+1)

    bool arow_ok = (row0 + am) < M;
    const __half* Aptr = A + (size_t)(row0 + am) * K + akh;
    const __half* Bp0  = Bh + (size_t)(2 * bq) * N + col0 + bn4;

    uint4 ar;
    uint2 b0r, b1r;
    ar  = arow_ok ? *(const uint4*)Aptr : make_uint4(0, 0, 0, 0);
    b0r = *(const uint2*)Bp0;
    b1r = *(const uint2*)(Bp0 + N);

    auto stage = [&](int buf) {
        As[buf][ak2 + 0][am] = ar.x;
        As[buf][ak2 + 1][am] = ar.y;
        As[buf][ak2 + 2][am] = ar.z;
        As[buf][ak2 + 3][am] = ar.w;
        uint4 bp;
        bp.x = __byte_perm(b0r.x, b1r.x, 0x5410);
        bp.y = __byte_perm(b0r.x, b1r.x, 0x7632);
        bp.z = __byte_perm(b0r.y, b1r.y, 0x5410);
        bp.w = __byte_perm(b0r.y, b1r.y, 0x7632);
        *(uint4*)&Bs[buf][bq][bn4] = bp;
    };

    stage(0);
    __syncthreads();

    float acc[2][8][4] = {};
    int nk = K / 16;
    int buf = 0;

    for (int t = 0; t < nk; t++) {
        if (t + 1 < nk) {
            const __half* Ap = Aptr + (t + 1) * 16;
            ar = arow_ok ? *(const uint4*)Ap : make_uint4(0, 0, 0, 0);
            const __half* Bp = Bp0 + (size_t)(t + 1) * 16 * N;
            b0r = *(const uint2*)Bp;
            b1r = *(const uint2*)(Bp + N);
        }
        uint32_t af[2][4], bf[8][2];
#pragma unroll
        for (int mt = 0; mt < 2; mt++) {
            int mb = wm * 32 + mt * 16 + r;
            af[mt][0] = As[buf][cq][mb];
            af[mt][1] = As[buf][cq][mb + 8];
            af[mt][2] = As[buf][cq + 4][mb];
            af[mt][3] = As[buf][cq + 4][mb + 8];
        }
#pragma unroll
        for (int nt = 0; nt < 8; nt++) {
            int nb = wn * 64 + nt * 8 + r;
            bf[nt][0] = Bs[buf][cq][nb];
            bf[nt][1] = Bs[buf][cq + 4][nb];
        }
#pragma unroll
        for (int mt = 0; mt < 2; mt++)
#pragma unroll
            for (int nt = 0; nt < 8; nt++)
                mma_f16(acc[mt][nt], af[mt], bf[nt]);

        if (t + 1 < nk) {
            buf ^= 1;
            stage(buf);
            __syncthreads();
        }
    }

    // epilogue: acc[mt][nt][{0,1}] -> row rA cols cb,cb+1 ; [{2,3}] -> row rA+8
#pragma unroll
    for (int mt = 0; mt < 2; mt++) {
        int rA = row0 + wm * 32 + mt * 16 + r;
        int rB = rA + 8;
        bool okA = rA < M, okB = rB < M;
        int pixA = -1, pixB = -1;
        if (MODE == 1) {
            if (okA) pixA = winrow_to_pixel(rA);
            if (okB) pixB = winrow_to_pixel(rB);
        }
#pragma unroll
        for (int nt = 0; nt < 8; nt++) {
            int cb = col0 + wn * 64 + nt * 8 + cq * 2;
#pragma unroll
            for (int half = 0; half < 2; half++) {
                int rr = half ? rB : rA;
                bool ok = half ? okB : okA;
                if (!ok) continue;
                float v0 = acc[mt][nt][half * 2 + 0] + bias[cb];
                float v1 = acc[mt][nt][half * 2 + 1] + bias[cb + 1];
                if (MODE == 0) {
                    Cf[(size_t)rr * N + cb]     = v0;
                    Cf[(size_t)rr * N + cb + 1] = v1;
                } else if (MODE == 1) {
                    int pix = half ? pixB : pixA;
                    if (pix >= 0) {
                        Cf[(size_t)pix * N + cb]     = aux[(size_t)pix * N + cb] + v0;
                        Cf[(size_t)pix * N + cb + 1] = aux[(size_t)pix * N + cb + 1] + v1;
                    }
                } else if (MODE == 2) {
                    float g0 = 0.5f * v0 * (1.f + erff(v0 * 0.70710678118654752f));
                    float g1 = 0.5f * v1 * (1.f + erff(v1 * 0.70710678118654752f));
                    *(half2*)(Ch + (size_t)rr * N + cb) = __floats2half2_rn(g0, g1);
                } else {
                    Cf[(size_t)rr * N + cb]     = aux[(size_t)rr * N + cb] + v0;
                    Cf[(size_t)rr * N + cb + 1] = aux[(size_t)rr * N + cb + 1] + v1;
                }
            }
        }
    }
}

// ---------------- fused attention: warp-per-query-PAIR --------------------
constexpr int QSPLIT = 2;
constexpr int QPB = L / QSPLIT;   // 98 (even)
constexpr int ATTN_SMEM_FLOATS =
    L * 65 +        // Ks (padded)
    L * 64 +        // Vs
    RELN * 65 +     // RH
    RELN * 65 +     // RW
    8 * 132 +       // per-warp q pair (2 x 66)
    8 * 400;        // per-warp probs (2 x 200)
constexpr int ATTN_SMEM_BYTES = ATTN_SMEM_FLOATS * 4;

__global__ void attn_kernel(const float* __restrict__ rph,
                            const float* __restrict__ rpw) {
    extern __shared__ float sm[];
    float* Ks = sm;
    float* Vs = Ks + L * 65;
    float* RH = Vs + L * 64;
    float* RW = RH + RELN * 65;
    float* qb = RW + RELN * 65;
    float* pb = qb + 8 * 132;

    int blk = blockIdx.x;
    int part = blk & (QSPLIT - 1);
    int wh = blk / QSPLIT;
    int nw = wh / HEADS, head = wh - nw * HEADS;
    int tid = threadIdx.x;
    size_t base = (size_t)nw * L * C3 + head * HD;

    for (int idx = tid; idx < L * HD; idx += 256) {
        int l = idx >> 6, d = idx & 63;
        Ks[l * 65 + d] = g_qkv[base + (size_t)l * C3 + C + d];
        Vs[l * 64 + d] = g_qkv[base + (size_t)l * C3 + 2 * C + d];
    }
    for (int idx = tid; idx < RELN * HD; idx += 256) {
        int r = idx >> 6, d = idx & 63;
        RH[r * 65 + d] = rph[idx];
        RW[r * 65 + d] = rpw[idx];
    }
    __syncthreads();

    int warp = tid >> 5, lane = tid & 31;
    float* qv0 = qb + warp * 132;
    float* qv1 = qv0 + 66;
    float* prob0 = pb + warp * 400;
    float* prob1 = prob0 + 200;
    int qend = (part + 1) * QPB;

    for (int q0 = part * QPB + warp * 2; q0 < qend; q0 += 16) {
        int q1 = q0 + 1;
        {
            float2 a = *(const float2*)&g_qkv[base + (size_t)q0 * C3 + lane * 2];
            float2 b = *(const float2*)&g_qkv[base + (size_t)q1 * C3 + lane * 2];
            *(float2*)&qv0[lane * 2] = a;
            *(float2*)&qv1[lane * 2] = b;
        }
        __syncwarp();

        int qi = q0 / WS, qj0 = q0 - qi * WS, qj1 = qj0 + 1;  // same row

        int koff[7], hoff[7], w0off[7], w1off[7];
        bool ok[7];
        float sA[7], sB[7], bhA[7], bhB[7], bwA[7], bwB[7];
#pragma unroll
        for (int s = 0; s < 7; s++) {
            int k = lane + 32 * s;
            ok[s] = (k < L);
            int kc = ok[s] ? k : (L - 1);
            int ki = kc / WS, kj = kc - ki * WS;
            koff[s]  = kc * 65;
            hoff[s]  = (qi - ki + WS - 1) * 65;
            w0off[s] = (qj0 - kj + WS - 1) * 65;
            w1off[s] = (qj1 - kj + WS - 1) * 65;
            sA[s] = 0.f; sB[s] = 0.f;
            bhA[s] = 0.f; bhB[s] = 0.f;
            bwA[s] = 0.f; bwB[s] = 0.f;
        }
#pragma unroll 4
        for (int d = 0; d < HD; d++) {
            float qa = qv0[d], qc = qv1[d];
#pragma unroll
            for (int s = 0; s < 7; s++) {
                float kv = Ks[koff[s] + d];
                float hv = RH[hoff[s] + d];
                sA[s]  = fmaf(qa, kv, sA[s]);
                sB[s]  = fmaf(qc, kv, sB[s]);
                bhA[s] = fmaf(qa, hv, bhA[s]);
                bhB[s] = fmaf(qc, hv, bhB[s]);
                bwA[s] = fmaf(qa, RW[w0off[s] + d], bwA[s]);
                bwB[s] = fmaf(qc, RW[w1off[s] + d], bwB[s]);
            }
        }
        float ltA[7], ltB[7];
#pragma unroll
        for (int s = 0; s < 7; s++) {
            ltA[s] = ok[s] ? (sA[s] * SCALE + bhA[s] + bwA[s]) : -1e30f;
            ltB[s] = ok[s] ? (sB[s] * SCALE + bhB[s] + bwB[s]) : -1e30f;
        }

        float mxA = ltA[0], mxB = ltB[0];
#pragma unroll
        for (int s = 1; s < 7; s++) { mxA = fmaxf(mxA, ltA[s]); mxB = fmaxf(mxB, ltB[s]); }
        for (int o = 16; o; o >>= 1) {
            mxA = fmaxf(mxA, __shfl_xor_sync(0xffffffffu, mxA, o));
            mxB = fmaxf(mxB, __shfl_xor_sync(0xffffffffu, mxB, o));
        }
        float smA = 0.f, smB = 0.f;
#pragma unroll
        for (int s = 0; s < 7; s++) {
            ltA[s] = expf(ltA[s] - mxA); smA += ltA[s];
            ltB[s] = expf(ltB[s] - mxB); smB += ltB[s];
        }
        for (int o = 16; o; o >>= 1) {
            smA += __shfl_xor_sync(0xffffffffu, smA, o);
            smB += __shfl_xor_sync(0xffffffffu, smB, o);
        }
        float ivA = 1.f / smA, ivB = 1.f / smB;
#pragma unroll
        for (int s = 0; s < 7; s++) {
            int k = lane + 32 * s;
            if (k < L) { prob0[k] = ltA[s] * ivA; prob1[k] = ltB[s] * ivB; }
        }
        __syncwarp();

        int d0 = lane * 2;
        float a0 = 0.f, a1 = 0.f, b0 = 0.f, b1 = 0.f;
#pragma unroll 4
        for (int k = 0; k < L; k++) {
            float2 v = *(const float2*)&Vs[k * 64 + d0];
            float pA = prob0[k], pB = prob1[k];
            a0 = fmaf(pA, v.x, a0);
            a1 = fmaf(pA, v.y, a1);
            b0 = fmaf(pB, v.x, b0);
            b1 = fmaf(pB, v.y, b1);
        }
        size_t orow = ((size_t)nw * L + q0) * C + head * HD + d0;
        *(half2*)&g_owin_h[orow]     = __floats2half2_rn(a0, a1);
        *(half2*)&g_owin_h[orow + C] = __floats2half2_rn(b0, b1);
        __syncwarp();
    }
}

// ---------------- launch ---------------------------------------------------
extern "C" void kernel_launch(void* const* d_in, const int* in_sizes, int n_in,
                              void* d_out, int out_size) {
    const float* x      = (const float*)d_in[0];
    const float* n1s    = (const float*)d_in[1];
    const float* n1b    = (const float*)d_in[2];
    const float* qkvw   = (const float*)d_in[3];
    const float* qkvb   = (const float*)d_in[4];
    const float* rph    = (const float*)d_in[5];
    const float* rpw    = (const float*)d_in[6];
    const float* projw  = (const float*)d_in[7];
    const float* projb  = (const float*)d_in[8];
    const float* n2s    = (const float*)d_in[9];
    const float* n2b    = (const float*)d_in[10];
    const float* fc1w   = (const float*)d_in[11];
    const float* fc1b   = (const float*)d_in[12];
    const float* fc2w   = (const float*)d_in[13];
    const float* fc2b   = (const float*)d_in[14];
    float* out = (float*)d_out;

    cudaFuncSetAttribute(attn_kernel, cudaFuncAttributeMaxDynamicSharedMemorySize,
                         ATTN_SMEM_BYTES);

    __half* ywin;  cudaGetSymbolAddress((void**)&ywin,  g_ywin_h);
    float*  qkv;   cudaGetSymbolAddress((void**)&qkv,   g_qkv);
    __half* owin;  cudaGetSymbolAddress((void**)&owin,  g_owin_h);
    float*  x1;    cudaGetSymbolAddress((void**)&x1,    g_x1);
    __half* h2;    cudaGetSymbolAddress((void**)&h2,    g_h2_h);
    __half* m1;    cudaGetSymbolAddress((void**)&m1,    g_m1_h);
    __half* qkvwh; cudaGetSymbolAddress((void**)&qkvwh, g_qkvw_h);
    __half* projwh;cudaGetSymbolAddress((void**)&projwh,g_projw_h);
    __half* fc1wh; cudaGetSymbolAddress((void**)&fc1wh, g_fc1w_h);
    __half* fc2wh; cudaGetSymbolAddress((void**)&fc2wh, g_fc2w_h);

    // 0) weights -> fp16 (cheap, once per launch)
    f2h_kernel<<<1024, 256>>>(qkvw,  qkvwh,  C * C3 / 2);
    f2h_kernel<<<512,  256>>>(projw, projwh, C * C / 2);
    f2h_kernel<<<1024, 256>>>(fc1w,  fc1wh,  C * HID / 2);
    f2h_kernel<<<1024, 256>>>(fc2w,  fc2wh,  HID * C / 2);

    // 1) LN1 + window partition (zero-pad), fp16 out
    ln1_gather_kernel<<<NT, 256>>>(x, n1s, n1b);

    // 2) qkv = ywin @ qkv_w + qkv_b           (19600 x 2304 x 768), fp32 out
    {
        dim3 grid(C3 / 128, (NT + 127) / 128);
        hgemm_kernel<0><<<grid, 256>>>(ywin, qkvwh, qkvb, nullptr, qkv, NT, C3, C);
    }

    // 3) fused windowed attention (warp-per-query-pair), fp16 out
    attn_kernel<<<NW * HEADS * QSPLIT, 256, ATTN_SMEM_BYTES>>>(rph, rpw);

    // 4) x1 = shortcut + (owin @ proj_w + proj_b)  (scatter, crop padding)
    {
        dim3 grid(C / 128, (NT + 127) / 128);
        hgemm_kernel<1><<<grid, 256>>>(owin, projwh, projb, x, x1, NT, C, C);
    }

    // 5) LN2 -> fp16
    ln_rows_kernel<<<NP, 256>>>(x1, n2s, n2b);

    // 6) m1 = gelu(h2 @ fc1_w + fc1_b)        (16384 x 3072 x 768), fp16 out
    {
        dim3 grid(HID / 128, NP / 128);
        hgemm_kernel<2><<<grid, 256>>>(h2, fc1wh, fc1b, nullptr, m1, NP, HID, C);
    }

    // 7) out = x1 + m1 @ fc2_w + fc2_b        (16384 x 768 x 3072), fp32 out
    {
        dim3 grid(C / 128, NP / 128);
        hgemm_kernel<3><<<grid, 256>>>(m1, fc2wh, fc2b, x1, out, NP, C, HID);
    }
}

// round 8
// speedup vs baseline: 5.0870x; 1.3601x over previous
#include <cuda_runtime.h>
#include <cuda_fp16.h>
#include <math.h>
#include <stdint.h>

// ---------------- problem constants ----------------
namespace {
constexpr int B = 4, H = 64, W = 64, C = 768;
constexpr int HEADS = 12, HD = 64, WS = 14, HID = 3072;
constexpr int NWIN = 5;               // 70/14
constexpr int NWB  = NWIN * NWIN;     // 25 windows per batch
constexpr int NW   = B * NWB;         // 100 windows
constexpr int L    = WS * WS;         // 196 tokens per window
constexpr int NT   = NW * L;          // 19600 window tokens
constexpr int NP   = B * H * W;       // 16384 real pixels
constexpr int C3   = 3 * C;           // 2304
constexpr int RELN = 2 * WS - 1;      // 27
constexpr float EPS   = 1e-6f;
constexpr float SCALE = 0.125f;       // HD^-0.5
}

// ---------------- scratch (device globals; no allocation allowed) --------
__device__ __half g_ywin_h[(size_t)NT * C];    // LN1 out (window layout, fp16)
__device__ float  g_qkv  [(size_t)NT * C3];    // qkv (fp32, attention input)
__device__ __half g_owin_h[(size_t)NT * C];    // attention out (fp16)
__device__ float  g_x1   [(size_t)NP * C];     // shortcut + proj(o)
__device__ __half g_h2_h [(size_t)NP * C];     // LN2 out (fp16)
__device__ __half g_m1_h [(size_t)NP * HID];   // gelu(fc1) (fp16)
// fp16 weight copies
__device__ __half g_qkvw_h[(size_t)C * C3];
__device__ __half g_projw_h[(size_t)C * C];
__device__ __half g_fc1w_h[(size_t)C * HID];
__device__ __half g_fc2w_h[(size_t)HID * C];

// window-row -> pixel-row index (-1 if padded)
__device__ __forceinline__ int winrow_to_pixel(int t) {
    int nw = t / L, l = t - nw * L;
    int b  = nw / NWB, r = nw - b * NWB;
    int wi = r / NWIN, wj = r - wi * NWIN;
    int i  = l / WS,   j  = l - i * WS;
    int hh = wi * WS + i, ww = wj * WS + j;
    if (hh >= H || ww >= W) return -1;
    return (b * H + hh) * W + ww;
}

__device__ __forceinline__ void mma_f16(float c[4], const uint32_t a[4],
                                        const uint32_t b[2]) {
    asm volatile(
        "mma.sync.aligned.m16n8k16.row.col.f32.f16.f16.f32 "
        "{%0,%1,%2,%3}, {%4,%5,%6,%7}, {%8,%9}, {%0,%1,%2,%3};"
        : "+f"(c[0]), "+f"(c[1]), "+f"(c[2]), "+f"(c[3])
        : "r"(a[0]), "r"(a[1]), "r"(a[2]), "r"(a[3]), "r"(b[0]), "r"(b[1]));
}

// ---------------- weight fp32 -> fp16 --------------------------------------
__global__ void f2h_kernel(const float* __restrict__ src,
                           __half* __restrict__ dst, int n2) {
    int i = blockIdx.x * blockDim.x + threadIdx.x;
    int stride = gridDim.x * blockDim.x;
    for (; i < n2; i += stride) {
        float2 v = ((const float2*)src)[i];
        ((half2*)dst)[i] = __floats2half2_rn(v.x, v.y);
    }
}

// ---------------- LN1 + window gather (fp16 out, zero-fill padding) -------
__global__ void ln1_gather_kernel(const float* __restrict__ x,
                                  const float* __restrict__ sc,
                                  const float* __restrict__ bi) {
    int t = blockIdx.x;
    int tid = threadIdx.x;
    __half* y = g_ywin_h + (size_t)t * C;
    int pix = winrow_to_pixel(t);
    if (pix < 0) {
        for (int c = tid; c < C; c += blockDim.x) y[c] = __float2half(0.f);
        return;
    }
    const float* xr = x + (size_t)pix * C;
    float s = 0.f, s2 = 0.f;
    for (int c = tid; c < C; c += blockDim.x) { float v = xr[c]; s += v; s2 += v * v; }
    __shared__ float red[64];
    for (int o = 16; o; o >>= 1) {
        s  += __shfl_xor_sync(0xffffffffu, s, o);
        s2 += __shfl_xor_sync(0xffffffffu, s2, o);
    }
    int warp = tid >> 5, lane = tid & 31;
    if (!lane) { red[warp] = s; red[32 + warp] = s2; }
    __syncthreads();
    if (tid < 32) {
        float a  = (tid < 8) ? red[tid]      : 0.f;
        float b2 = (tid < 8) ? red[32 + tid] : 0.f;
        for (int o = 4; o; o >>= 1) {
            a  += __shfl_xor_sync(0xffffffffu, a, o);
            b2 += __shfl_xor_sync(0xffffffffu, b2, o);
        }
        if (!tid) { red[0] = a; red[1] = b2; }
    }
    __syncthreads();
    float mu  = red[0] / (float)C;
    float var = red[1] / (float)C - mu * mu;
    float inv = rsqrtf(var + EPS);
    for (int c = tid; c < C; c += blockDim.x)
        y[c] = __float2half((xr[c] - mu) * inv * sc[c] + bi[c]);
}

// ---------------- LN over contiguous rows (x1 -> h2 fp16) -----------------
__global__ void ln_rows_kernel(const float* __restrict__ in,
                               const float* __restrict__ sc,
                               const float* __restrict__ bi) {
    int t = blockIdx.x;
    int tid = threadIdx.x;
    const float* xr = in + (size_t)t * C;
    __half* y = g_h2_h + (size_t)t * C;
    float s = 0.f, s2 = 0.f;
    for (int c = tid; c < C; c += blockDim.x) { float v = xr[c]; s += v; s2 += v * v; }
    __shared__ float red[64];
    for (int o = 16; o; o >>= 1) {
        s  += __shfl_xor_sync(0xffffffffu, s, o);
        s2 += __shfl_xor_sync(0xffffffffu, s2, o);
    }
    int warp = tid >> 5, lane = tid & 31;
    if (!lane) { red[warp] = s; red[32 + warp] = s2; }
    __syncthreads();
    if (tid < 32) {
        float a  = (tid < 8) ? red[tid]      : 0.f;
        float b2 = (tid < 8) ? red[32 + tid] : 0.f;
        for (int o = 4; o; o >>= 1) {
            a  += __shfl_xor_sync(0xffffffffu, a, o);
            b2 += __shfl_xor_sync(0xffffffffu, b2, o);
        }
        if (!tid) { red[0] = a; red[1] = b2; }
    }
    __syncthreads();
    float mu  = red[0] / (float)C;
    float var = red[1] / (float)C - mu * mu;
    float inv = rsqrtf(var + EPS);
    for (int c = tid; c < C; c += blockDim.x)
        y[c] = __float2half((xr[c] - mu) * inv * sc[c] + bi[c]);
}

// ---------------- fp16 tensor-core GEMM (mma.sync m16n8k16) ---------------
template <int MODE>
__global__ void __launch_bounds__(256, 2)
hgemm_kernel(const __half* __restrict__ A,
             const __half* __restrict__ Bh,
             const float* __restrict__ bias,
             const float* __restrict__ aux,
             void* __restrict__ CoutV,
             int M, int N, int K) {
    constexpr int SP = 136;
    __shared__ uint32_t As[2][8][SP];   // [k2][m] half2(k even, k odd)
    __shared__ uint32_t Bs[2][8][SP];   // [k2][n]
    float*  Cf = (float*)CoutV;
    __half* Ch = (__half*)CoutV;

    int tid  = threadIdx.x;
    int warp = tid >> 5, lane = tid & 31;
    int wm = warp >> 1, wn = warp & 1;     // 4 x 2 warp grid
    int row0 = blockIdx.y * 128, col0 = blockIdx.x * 128;
    int r = lane >> 2, cq = lane & 3;

    int am  = tid & 127;
    int ak2 = (tid >> 7) * 4;            // k2 base: 0 or 4
    int akh = ak2 * 2;                   // half offset: 0 or 8
    int bn4 = (tid & 31) * 4;
    int bq  = tid >> 5;                  // k2 row 0..7 (k rows 2bq, 2bq+1)

    bool arow_ok = (row0 + am) < M;
    const __half* Aptr = A + (size_t)(row0 + am) * K + akh;
    const __half* Bp0  = Bh + (size_t)(2 * bq) * N + col0 + bn4;

    uint4 ar;
    uint2 b0r, b1r;
    ar  = arow_ok ? *(const uint4*)Aptr : make_uint4(0, 0, 0, 0);
    b0r = *(const uint2*)Bp0;
    b1r = *(const uint2*)(Bp0 + N);

    auto stage = [&](int buf) {
        As[buf][ak2 + 0][am] = ar.x;
        As[buf][ak2 + 1][am] = ar.y;
        As[buf][ak2 + 2][am] = ar.z;
        As[buf][ak2 + 3][am] = ar.w;
        uint4 bp;
        bp.x = __byte_perm(b0r.x, b1r.x, 0x5410);
        bp.y = __byte_perm(b0r.x, b1r.x, 0x7632);
        bp.z = __byte_perm(b0r.y, b1r.y, 0x5410);
        bp.w = __byte_perm(b0r.y, b1r.y, 0x7632);
        *(uint4*)&Bs[buf][bq][bn4] = bp;
    };

    stage(0);
    __syncthreads();

    float acc[2][8][4] = {};
    int nk = K / 16;
    int buf = 0;

    for (int t = 0; t < nk; t++) {
        if (t + 1 < nk) {
            const __half* Ap = Aptr + (t + 1) * 16;
            ar = arow_ok ? *(const uint4*)Ap : make_uint4(0, 0, 0, 0);
            const __half* Bp = Bp0 + (size_t)(t + 1) * 16 * N;
            b0r = *(const uint2*)Bp;
            b1r = *(const uint2*)(Bp + N);
        }
        uint32_t af[2][4], bf[8][2];
#pragma unroll
        for (int mt = 0; mt < 2; mt++) {
            int mb = wm * 32 + mt * 16 + r;
            af[mt][0] = As[buf][cq][mb];
            af[mt][1] = As[buf][cq][mb + 8];
            af[mt][2] = As[buf][cq + 4][mb];
            af[mt][3] = As[buf][cq + 4][mb + 8];
        }
#pragma unroll
        for (int nt = 0; nt < 8; nt++) {
            int nb = wn * 64 + nt * 8 + r;
            bf[nt][0] = Bs[buf][cq][nb];
            bf[nt][1] = Bs[buf][cq + 4][nb];
        }
#pragma unroll
        for (int mt = 0; mt < 2; mt++)
#pragma unroll
            for (int nt = 0; nt < 8; nt++)
                mma_f16(acc[mt][nt], af[mt], bf[nt]);

        if (t + 1 < nk) {
            buf ^= 1;
            stage(buf);
            __syncthreads();
        }
    }

#pragma unroll
    for (int mt = 0; mt < 2; mt++) {
        int rA = row0 + wm * 32 + mt * 16 + r;
        int rB = rA + 8;
        bool okA = rA < M, okB = rB < M;
        int pixA = -1, pixB = -1;
        if (MODE == 1) {
            if (okA) pixA = winrow_to_pixel(rA);
            if (okB) pixB = winrow_to_pixel(rB);
        }
#pragma unroll
        for (int nt = 0; nt < 8; nt++) {
            int cb = col0 + wn * 64 + nt * 8 + cq * 2;
#pragma unroll
            for (int half = 0; half < 2; half++) {
                int rr = half ? rB : rA;
                bool ok = half ? okB : okA;
                if (!ok) continue;
                float v0 = acc[mt][nt][half * 2 + 0] + bias[cb];
                float v1 = acc[mt][nt][half * 2 + 1] + bias[cb + 1];
                if (MODE == 0) {
                    Cf[(size_t)rr * N + cb]     = v0;
                    Cf[(size_t)rr * N + cb + 1] = v1;
                } else if (MODE == 1) {
                    int pix = half ? pixB : pixA;
                    if (pix >= 0) {
                        Cf[(size_t)pix * N + cb]     = aux[(size_t)pix * N + cb] + v0;
                        Cf[(size_t)pix * N + cb + 1] = aux[(size_t)pix * N + cb + 1] + v1;
                    }
                } else if (MODE == 2) {
                    float g0 = 0.5f * v0 * (1.f + erff(v0 * 0.70710678118654752f));
                    float g1 = 0.5f * v1 * (1.f + erff(v1 * 0.70710678118654752f));
                    *(half2*)(Ch + (size_t)rr * N + cb) = __floats2half2_rn(g0, g1);
                } else {
                    Cf[(size_t)rr * N + cb]     = aux[(size_t)rr * N + cb] + v0;
                    Cf[(size_t)rr * N + cb + 1] = aux[(size_t)rr * N + cb + 1] + v1;
                }
            }
        }
    }
}

// ---------------- fused attention v3 ---------------------------------------
// warp-per-query-pair; K/V fp16 half2 in smem; decomposed rel-pos bias
// (14+14 dots per query instead of per-key recompute). 2 CTAs/SM (84KB).
constexpr int ATTN_SMEM_U32 =
    L * 33 +        // Ks2 half2 [l*33 + d2], pad stride 33
    L * 32 +        // Vs2 half2 [k*32 + lane]
    RELN * 66 +     // RH fp32 (stride 66 for float2 align)
    RELN * 66 +     // RW fp32
    8 * 132 +       // per-warp q pair (2 x 66 fp32)
    8 * 400 +       // per-warp probs (2 x 200 fp32)
    8 * 64;         // per-warp bias dots (bhA[14] bhB[14] | bwA[14] bwB[14])
constexpr int ATTN_SMEM_BYTES = ATTN_SMEM_U32 * 4;

__global__ void attn_kernel(const float* __restrict__ rph,
                            const float* __restrict__ rpw) {
    extern __shared__ uint32_t smu[];
    half2* Ks2 = (half2*)smu;                  // [l*33 + d2]
    half2* Vs2 = Ks2 + L * 33;                 // [k*32 + lane]
    float* RH = (float*)(Vs2 + L * 32);
    float* RW = RH + RELN * 66;
    float* qb = RW + RELN * 66;
    float* pb = qb + 8 * 132;
    float* bb = pb + 8 * 400;

    int wh = blockIdx.x;
    int nw = wh / HEADS, head = wh - nw * HEADS;
    int tid = threadIdx.x;
    size_t base = (size_t)nw * L * C3 + head * HD;

    // stage K,V as half2 (32 half2 per row)
    for (int idx = tid; idx < L * 32; idx += 256) {
        int l = idx >> 5, d2 = idx & 31;
        float2 kv = *(const float2*)&g_qkv[base + (size_t)l * C3 + C + 2 * d2];
        float2 vv = *(const float2*)&g_qkv[base + (size_t)l * C3 + 2 * C + 2 * d2];
        Ks2[l * 33 + d2] = __floats2half2_rn(kv.x, kv.y);
        Vs2[l * 32 + d2] = __floats2half2_rn(vv.x, vv.y);
    }
    for (int idx = tid; idx < RELN * HD; idx += 256) {
        int r = idx >> 6, d = idx & 63;
        RH[r * 66 + d] = rph[idx];
        RW[r * 66 + d] = rpw[idx];
    }
    __syncthreads();

    int warp = tid >> 5, lane = tid & 31;
    float* qv0 = qb + warp * 132;
    float* qv1 = qv0 + 66;
    float* prob0 = pb + warp * 400;
    float* prob1 = prob0 + 200;
    float* bw_ = bb + warp * 64;   // [0..13] bhA, [14..27] bhB, [32..45] bwA, [46..59] bwB

    // static per-lane key-slot info
    int koff[7];
    int kiL[7], kjL[7];
    bool ok[7];
#pragma unroll
    for (int s = 0; s < 7; s++) {
        int k = lane + 32 * s;
        ok[s] = (k < L);
        int kc = ok[s] ? k : (L - 1);
        kiL[s] = kc / WS;
        kjL[s] = kc - kiL[s] * WS;
        koff[s] = kc * 33;
    }

    for (int p = warp; p < L / 2; p += 8) {
        int q0 = 2 * p, q1 = q0 + 1;
        {
            float2 a = *(const float2*)&g_qkv[base + (size_t)q0 * C3 + lane * 2];
            float2 b = *(const float2*)&g_qkv[base + (size_t)q1 * C3 + lane * 2];
            *(float2*)&qv0[lane * 2] = a;
            *(float2*)&qv1[lane * 2] = b;
        }
        __syncwarp();

        int qi = q0 / WS, qj0 = q0 - qi * WS, qj1 = qj0 + 1;  // same row

        // ---- bias dots: lanes 0..27 each do one bh dot and one bw dot ----
        if (lane < 28) {
            int ksub = lane % 14;         // ki (for bh) / kj (for bw)
            int qsel = lane / 14;         // 0 -> q0, 1 -> q1
            const float* qp = qsel ? qv1 : qv0;
            const float* hp = RH + (qi - ksub + WS - 1) * 66;
            int qj = qsel ? qj1 : qj0;
            const float* wp = RW + (qj - ksub + WS - 1) * 66;
            float d1 = 0.f, d2a = 0.f;
#pragma unroll 8
            for (int d2 = 0; d2 < 32; d2++) {
                float2 q2 = *(const float2*)&qp[2 * d2];
                float2 h2 = *(const float2*)&hp[2 * d2];
                float2 w2 = *(const float2*)&wp[2 * d2];
                d1  = fmaf(q2.x, h2.x, d1);  d1  = fmaf(q2.y, h2.y, d1);
                d2a = fmaf(q2.x, w2.x, d2a); d2a = fmaf(q2.y, w2.y, d2a);
            }
            bw_[qsel * 14 + ksub] = d1;
            bw_[32 + qsel * 14 + ksub] = d2a;
        }
        __syncwarp();

        // ---- main QK: 7 key slots, fp16 K ----
        float sA[7] = {}, sB[7] = {};
#pragma unroll 8
        for (int d2 = 0; d2 < 32; d2++) {
            float2 qa2 = *(const float2*)&qv0[2 * d2];
            float2 qc2 = *(const float2*)&qv1[2 * d2];
#pragma unroll
            for (int s = 0; s < 7; s++) {
                float2 kf = __half22float2(Ks2[koff[s] + d2]);
                sA[s] = fmaf(qa2.x, kf.x, sA[s]);
                sA[s] = fmaf(qa2.y, kf.y, sA[s]);
                sB[s] = fmaf(qc2.x, kf.x, sB[s]);
                sB[s] = fmaf(qc2.y, kf.y, sB[s]);
            }
        }
        float ltA[7], ltB[7];
#pragma unroll
        for (int s = 0; s < 7; s++) {
            float bhA = bw_[kiL[s]],        bhB = bw_[14 + kiL[s]];
            float bwA = bw_[32 + kjL[s]],   bwB = bw_[46 + kjL[s]];
            ltA[s] = ok[s] ? (sA[s] * SCALE + bhA + bwA) : -1e30f;
            ltB[s] = ok[s] ? (sB[s] * SCALE + bhB + bwB) : -1e30f;
        }

        // ---- softmax ----
        float mxA = ltA[0], mxB = ltB[0];
#pragma unroll
        for (int s = 1; s < 7; s++) { mxA = fmaxf(mxA, ltA[s]); mxB = fmaxf(mxB, ltB[s]); }
        for (int o = 16; o; o >>= 1) {
            mxA = fmaxf(mxA, __shfl_xor_sync(0xffffffffu, mxA, o));
            mxB = fmaxf(mxB, __shfl_xor_sync(0xffffffffu, mxB, o));
        }
        float smA = 0.f, smB = 0.f;
#pragma unroll
        for (int s = 0; s < 7; s++) {
            ltA[s] = expf(ltA[s] - mxA); smA += ltA[s];
            ltB[s] = expf(ltB[s] - mxB); smB += ltB[s];
        }
        for (int o = 16; o; o >>= 1) {
            smA += __shfl_xor_sync(0xffffffffu, smA, o);
            smB += __shfl_xor_sync(0xffffffffu, smB, o);
        }
        float ivA = 1.f / smA, ivB = 1.f / smB;
#pragma unroll
        for (int s = 0; s < 7; s++) {
            int k = lane + 32 * s;
            if (k < L) { prob0[k] = ltA[s] * ivA; prob1[k] = ltB[s] * ivB; }
        }
        __syncwarp();

        // ---- AV: lane owns dims (2*lane, 2*lane+1); V fp16 ----
        float a0 = 0.f, a1 = 0.f, b0 = 0.f, b1 = 0.f;
#pragma unroll 4
        for (int k = 0; k < L; k++) {
            float2 vf = __half22float2(Vs2[k * 32 + lane]);
            float pA = prob0[k], pB = prob1[k];
            a0 = fmaf(pA, vf.x, a0);
            a1 = fmaf(pA, vf.y, a1);
            b0 = fmaf(pB, vf.x, b0);
            b1 = fmaf(pB, vf.y, b1);
        }
        size_t orow = ((size_t)nw * L + q0) * C + head * HD + lane * 2;
        *(half2*)&g_owin_h[orow]     = __floats2half2_rn(a0, a1);
        *(half2*)&g_owin_h[orow + C] = __floats2half2_rn(b0, b1);
        __syncwarp();
    }
}

// ---------------- launch ---------------------------------------------------
extern "C" void kernel_launch(void* const* d_in, const int* in_sizes, int n_in,
                              void* d_out, int out_size) {
    const float* x      = (const float*)d_in[0];
    const float* n1s    = (const float*)d_in[1];
    const float* n1b    = (const float*)d_in[2];
    const float* qkvw   = (const float*)d_in[3];
    const float* qkvb   = (const float*)d_in[4];
    const float* rph    = (const float*)d_in[5];
    const float* rpw    = (const float*)d_in[6];
    const float* projw  = (const float*)d_in[7];
    const float* projb  = (const float*)d_in[8];
    const float* n2s    = (const float*)d_in[9];
    const float* n2b    = (const float*)d_in[10];
    const float* fc1w   = (const float*)d_in[11];
    const float* fc1b   = (const float*)d_in[12];
    const float* fc2w   = (const float*)d_in[13];
    const float* fc2b   = (const float*)d_in[14];
    float* out = (float*)d_out;

    cudaFuncSetAttribute(attn_kernel, cudaFuncAttributeMaxDynamicSharedMemorySize,
                         ATTN_SMEM_BYTES);

    __half* ywin;  cudaGetSymbolAddress((void**)&ywin,  g_ywin_h);
    float*  qkv;   cudaGetSymbolAddress((void**)&qkv,   g_qkv);
    __half* owin;  cudaGetSymbolAddress((void**)&owin,  g_owin_h);
    float*  x1;    cudaGetSymbolAddress((void**)&x1,    g_x1);
    __half* h2;    cudaGetSymbolAddress((void**)&h2,    g_h2_h);
    __half* m1;    cudaGetSymbolAddress((void**)&m1,    g_m1_h);
    __half* qkvwh; cudaGetSymbolAddress((void**)&qkvwh, g_qkvw_h);
    __half* projwh;cudaGetSymbolAddress((void**)&projwh,g_projw_h);
    __half* fc1wh; cudaGetSymbolAddress((void**)&fc1wh, g_fc1w_h);
    __half* fc2wh; cudaGetSymbolAddress((void**)&fc2wh, g_fc2w_h);

    // 0) weights -> fp16
    f2h_kernel<<<1024, 256>>>(qkvw,  qkvwh,  C * C3 / 2);
    f2h_kernel<<<512,  256>>>(projw, projwh, C * C / 2);
    f2h_kernel<<<1024, 256>>>(fc1w,  fc1wh,  C * HID / 2);
    f2h_kernel<<<1024, 256>>>(fc2w,  fc2wh,  HID * C / 2);

    // 1) LN1 + window partition (zero-pad), fp16 out
    ln1_gather_kernel<<<NT, 256>>>(x, n1s, n1b);

    // 2) qkv = ywin @ qkv_w + qkv_b           (19600 x 2304 x 768), fp32 out
    {
        dim3 grid(C3 / 128, (NT + 127) / 128);
        hgemm_kernel<0><<<grid, 256>>>(ywin, qkvwh, qkvb, nullptr, qkv, NT, C3, C);
    }

    // 3) fused windowed attention v3, fp16 out
    attn_kernel<<<NW * HEADS, 256, ATTN_SMEM_BYTES>>>(rph, rpw);

    // 4) x1 = shortcut + (owin @ proj_w + proj_b)  (scatter, crop padding)
    {
        dim3 grid(C / 128, (NT + 127) / 128);
        hgemm_kernel<1><<<grid, 256>>>(owin, projwh, projb, x, x1, NT, C, C);
    }

    // 5) LN2 -> fp16
    ln_rows_kernel<<<NP, 256>>>(x1, n2s, n2b);

    // 6) m1 = gelu(h2 @ fc1_w + fc1_b)        (16384 x 3072 x 768), fp16 out
    {
        dim3 grid(HID / 128, NP / 128);
        hgemm_kernel<2><<<grid, 256>>>(h2, fc1wh, fc1b, nullptr, m1, NP, HID, C);
    }

    // 7) out = x1 + m1 @ fc2_w + fc2_b        (16384 x 768 x 3072), fp32 out
    {
        dim3 grid(C / 128, NP / 128);
        hgemm_kernel<3><<<grid, 256>>>(m1, fc2wh, fc2b, x1, out, NP, C, HID);
    }
}